// round 11
// baseline (speedup 1.0000x reference)
#include <cuda_runtime.h>
#include <cuda_bf16.h>
#include <math.h>

#define NN 50000
#define EE 800000
#define BB 64
#define OBSD 128
#define MHD 256
#define NAD 16

// ---------------- scratch ----------------
__device__ float          g_x[NN * 128];
__device__ __nv_bfloat16  g_h[NN * 128];
__device__ float g_as[NN * 2];
__device__ float g_ad[NN * 2];
__device__ int   g_deg[NN + 1];
__device__ int   g_off[NN + 1];
__device__ int   g_cur[NN];
__device__ int   g_csr[EE];
__device__ float g_pool[BB * 64];

__device__ __forceinline__ float lrelu(float v) { return v > 0.f ? v : 0.2f * v; }

__device__ __forceinline__ void red4(float* p, float a, float b, float c, float d) {
    asm volatile("red.global.add.v4.f32 [%0], {%1,%2,%3,%4};"
                 :: "l"(p), "f"(a), "f"(b), "f"(c), "f"(d) : "memory");
}

// bf16 helpers
__device__ __forceinline__ void st_h4(__nv_bfloat16* p, const float* f) {
    uint2 u;
    *reinterpret_cast<__nv_bfloat162*>(&u.x) = __floats2bfloat162_rn(f[0], f[1]);
    *reinterpret_cast<__nv_bfloat162*>(&u.y) = __floats2bfloat162_rn(f[2], f[3]);
    *reinterpret_cast<uint2*>(p) = u;
}
__device__ __forceinline__ void st_h2(__nv_bfloat16* p, const float* f) {
    unsigned u;
    *reinterpret_cast<__nv_bfloat162*>(&u) = __floats2bfloat162_rn(f[0], f[1]);
    *reinterpret_cast<unsigned*>(p) = u;
}
__device__ __forceinline__ void acc_h4(float* acc, unsigned ux, unsigned uy, float w) {
    float2 lo = __bfloat1622float2(*reinterpret_cast<__nv_bfloat162*>(&ux));
    float2 hi = __bfloat1622float2(*reinterpret_cast<__nv_bfloat162*>(&uy));
    acc[0] += w * lo.x; acc[1] += w * lo.y; acc[2] += w * hi.x; acc[3] += w * hi.y;
}
__device__ __forceinline__ void acc_h2(float* acc, unsigned u, float w) {
    float2 lo = __bfloat1622float2(*reinterpret_cast<__nv_bfloat162*>(&u));
    acc[0] += w * lo.x; acc[1] += w * lo.y;
}

// =================== fused: edge histogram + layer-0 GEMM (independent work) ===================
#define G0B 782
__global__ void __launch_bounds__(256) k_hg0(const int* __restrict__ ei,
                                             const float* __restrict__ xin,
                                             const float* __restrict__ W,
                                             const float* __restrict__ asrc,
                                             const float* __restrict__ adst) {
    __shared__ float Wsh[8 * 128];
    __shared__ float wfsh[32];
    __shared__ float wred[256];
    int tid = threadIdx.x;

    if (blockIdx.x < G0B) {
        // ---- gemm0 half ----
        int lane = tid & 31, wp = tid >> 5;
        for (int i = tid; i < 8 * 128; i += 256) Wsh[i] = W[i];
        __syncthreads();
        // parallel fold: dot d = tid>>3 (32 dots), elem slice e = tid&7
        {
            int d = tid >> 3, e = tid & 7;
            int a = d >> 3, k = d & 7, h = a & 1;
            const float* av = ((a < 2) ? asrc : adst) + h * 64;
            const float* wr = &Wsh[k * 128 + h * 64];
            float s = 0.f;
#pragma unroll
            for (int c = 0; c < 8; c++) s += wr[e + c * 8] * av[e + c * 8];
            wred[tid] = s;
        }
        __syncthreads();
        if (tid < 32) {
            float s = 0.f;
#pragma unroll
            for (int e = 0; e < 8; e++) s += wred[tid * 8 + e];
            wfsh[tid] = s;
        }
        __syncthreads();

        const int stride = G0B * 8;
        int node = blockIdx.x * 8 + wp;
        float4 pa, pb;
        if (node < NN) {
            pa = *reinterpret_cast<const float4*>(&xin[node * 8]);
            pb = *reinterpret_cast<const float4*>(&xin[node * 8 + 4]);
        }
        while (node < NN) {
            float4 xa = pa, xb = pb;
            int nnext = node + stride;
            if (nnext < NN) {   // prefetch next node's x
                pa = *reinterpret_cast<const float4*>(&xin[nnext * 8]);
                pb = *reinterpret_cast<const float4*>(&xin[nnext * 8 + 4]);
            }
            float xk[8] = {xa.x, xa.y, xa.z, xa.w, xb.x, xb.y, xb.z, xb.w};
            float acc[4] = {0.f, 0.f, 0.f, 0.f};
#pragma unroll
            for (int k = 0; k < 8; k++) {
                float4 w = *reinterpret_cast<const float4*>(&Wsh[k * 128 + lane * 4]);
                acc[0] += xk[k] * w.x; acc[1] += xk[k] * w.y;
                acc[2] += xk[k] * w.z; acc[3] += xk[k] * w.w;
            }
            st_h4(&g_h[(size_t)node * 128 + lane * 4], acc);

            int a = lane & 3;
            float s = 0.f;
#pragma unroll
            for (int k = 0; k < 8; k++) s += xk[k] * wfsh[a * 8 + k];
            if (lane < 2)      g_as[node * 2 + lane] = s;
            else if (lane < 4) g_ad[node * 2 + lane - 2] = s;
            node = nnext;
        }
    } else {
        // ---- histogram half ----
        const int4* d4 = reinterpret_cast<const int4*>(ei + EE);
        for (int i = (blockIdx.x - G0B) * 256 + tid; i < EE / 4; i += G0B * 256) {
            int4 v = d4[i];
            atomicAdd(&g_deg[v.x], 1);
            atomicAdd(&g_deg[v.y], 1);
            atomicAdd(&g_deg[v.z], 1);
            atomicAdd(&g_deg[v.w], 1);
        }
    }
}

// =================== CSR scan + fill ===================
__global__ void k_scan() {
    __shared__ int sh[1024];
    const int PER = 49;
    int tid = threadIdx.x;
    int base = tid * PER;
    int s = 0;
    for (int k = 0; k < PER; k++) {
        int i = base + k;
        if (i < NN) s += g_deg[i];
    }
    sh[tid] = s;
    __syncthreads();
    for (int o = 1; o < 1024; o <<= 1) {
        int t = (tid >= o) ? sh[tid - o] : 0;
        __syncthreads();
        sh[tid] += t;
        __syncthreads();
    }
    int run = sh[tid] - s;
    for (int k = 0; k < PER; k++) {
        int i = base + k;
        if (i < NN) {
            int d = g_deg[i];
            g_off[i] = run;
            g_cur[i] = run;
            run += d;
        }
    }
    if (tid == 0) g_off[NN] = EE;
}
__global__ void k_fill(const int* __restrict__ ei) {
    const int4* s4 = reinterpret_cast<const int4*>(ei);
    const int4* d4 = reinterpret_cast<const int4*>(ei + EE);
    for (int i = blockIdx.x * blockDim.x + threadIdx.x; i < EE / 4; i += gridDim.x * blockDim.x) {
        int4 s = s4[i];
        int4 d = d4[i];
        g_csr[atomicAdd(&g_cur[d.x], 1)] = s.x;
        g_csr[atomicAdd(&g_cur[d.y], 1)] = s.y;
        g_csr[atomicAdd(&g_cur[d.z], 1)] = s.z;
        g_csr[atomicAdd(&g_cur[d.w], 1)] = s.w;
    }
}

// =================== epilogue helper: alpha dots (layer 1/2 GEMM) ===================
template <int H, int VEC>
__device__ __forceinline__ void alpha_epilogue(int node, int lane, int head,
                                               const float* acc, const float* asv, const float* adv) {
    float vs = 0.f, vd = 0.f;
#pragma unroll
    for (int v = 0; v < VEC; v++) { vs += acc[v] * asv[v]; vd += acc[v] * adv[v]; }
    constexpr int RO = (H == 2) ? 8 : 16;
#pragma unroll
    for (int o = RO; o > 0; o >>= 1) {
        vs += __shfl_down_sync(0xffffffffu, vs, o);
        vd += __shfl_down_sync(0xffffffffu, vd, o);
    }
    if ((lane & ((H == 2) ? 15 : 31)) == 0) {
        g_as[node * H + head] = vs;
        g_ad[node * H + head] = vd;
    }
}

// =================== big GEMM (FIN=128 -> HC, H) ===================
template <int HC, int H>
__global__ void k_gemm128(const float* __restrict__ W,
                          const float* __restrict__ asrc, const float* __restrict__ adst) {
    constexpr int VEC = HC / 32;
    constexpr int KT = 32;
    constexpr int NCH = 64;
    __shared__ float Wsh[KT * HC];
    __shared__ float xsh[NCH * KT];
    int tid = threadIdx.x, lane = tid & 31, wp = tid >> 5;   // 8 warps
    int head = (H == 2) ? (lane >> 4) : 0;
    float asv[VEC], adv[VEC];
#pragma unroll
    for (int v = 0; v < VEC; v++) { asv[v] = asrc[lane * VEC + v]; adv[v] = adst[lane * VEC + v]; }

    for (int base = blockIdx.x * NCH; base < NN; base += gridDim.x * NCH) {
        float acc[8][VEC];
#pragma unroll
        for (int n = 0; n < 8; n++)
#pragma unroll
            for (int v = 0; v < VEC; v++) acc[n][v] = 0.f;

        for (int k0 = 0; k0 < 128; k0 += KT) {
            for (int i = tid; i < KT * HC; i += 256)
                Wsh[i] = W[((i / HC) + k0) * HC + (i % HC)];
            for (int i = tid; i < NCH * KT; i += 256) {
                int n = base + i / KT;
                xsh[i] = (n < NN) ? g_x[(size_t)n * 128 + k0 + (i % KT)] : 0.f;
            }
            __syncthreads();
#pragma unroll
            for (int kk = 0; kk < KT; kk += 4) {
                float wv[4][VEC];
#pragma unroll
                for (int j = 0; j < 4; j++)
#pragma unroll
                    for (int v = 0; v < VEC; v++)
                        wv[j][v] = Wsh[(kk + j) * HC + lane * VEC + v];
#pragma unroll
                for (int n = 0; n < 8; n++) {
                    float4 xv = *reinterpret_cast<const float4*>(&xsh[(wp * 8 + n) * KT + kk]);
#pragma unroll
                    for (int v = 0; v < VEC; v++)
                        acc[n][v] += xv.x * wv[0][v] + xv.y * wv[1][v]
                                   + xv.z * wv[2][v] + xv.w * wv[3][v];
                }
            }
            __syncthreads();
        }

#pragma unroll
        for (int n = 0; n < 8; n++) {
            int node = base + wp * 8 + n;
            if (node >= NN) break;
            if (VEC == 4) st_h4(&g_h[(size_t)node * HC + lane * 4], acc[n]);
            else          st_h2(&g_h[(size_t)node * HC + lane * 2], acc[n]);
            alpha_epilogue<H, VEC>(node, lane, head, acc[n], asv, adv);
        }
    }
}

// =================== fused softmax-aggregate (warp per dst node) ===================
template <int HC, int H, bool ACT, bool POOL>
__global__ void __launch_bounds__(256) k_agg(const float* __restrict__ bias,
                                             const int* __restrict__ batch) {
    constexpr int VEC = HC / 32;
    __shared__ int   s_s[8][32];
    __shared__ float s_w[8][32 * H];
    int lane = threadIdx.x & 31, wp = threadIdx.x >> 5;
    int node = blockIdx.x * 8 + wp;
    if (node >= NN) return;
    int head = (H == 2) ? (lane >> 4) : 0;

    float ad0 = g_ad[node * H];
    float ad1 = (H == 2) ? g_ad[node * H + 1] : 0.f;
    int beg = g_off[node], end = g_off[node + 1];

    float acc[VEC];
#pragma unroll
    for (int v = 0; v < VEC; v++) acc[v] = 0.f;
    float d0 = 0.f, d1 = 0.f;

    const __nv_bfloat16* __restrict__ hbase = g_h;

    for (int chunk = beg; chunk < end; chunk += 32) {
        int i = chunk + lane;
        if (i < end) {
            int s = g_csr[i];
            s_s[wp][lane] = s;
            if (H == 2) {
                float2 a = *reinterpret_cast<const float2*>(&g_as[s * 2]);
                float w0 = expf(lrelu(a.x + ad0));
                float w1 = expf(lrelu(a.y + ad1));
                d0 += w0; d1 += w1;
                s_w[wp][lane * 2]     = w0;
                s_w[wp][lane * 2 + 1] = w1;
            } else {
                float w0 = expf(lrelu(g_as[s] + ad0));
                d0 += w0;
                s_w[wp][lane] = w0;
            }
        }
        __syncwarp();
        int cnt = min(32, end - chunk);
        int j = 0;
        for (; j + 8 <= cnt; j += 8) {
            int   ss[8];
            float ww[8];
#pragma unroll
            for (int u = 0; u < 8; u++) {
                ss[u] = s_s[wp][j + u];
                ww[u] = (H == 2) ? s_w[wp][(j + u) * 2 + head] : s_w[wp][j + u];
            }
            if (VEC == 4) {
                uint2 hv[8];
#pragma unroll
                for (int u = 0; u < 8; u++)
                    hv[u] = *reinterpret_cast<const uint2*>(&hbase[(size_t)ss[u] * HC + lane * 4]);
#pragma unroll
                for (int u = 0; u < 8; u++) acc_h4(acc, hv[u].x, hv[u].y, ww[u]);
            } else {
                unsigned hv[8];
#pragma unroll
                for (int u = 0; u < 8; u++)
                    hv[u] = *reinterpret_cast<const unsigned*>(&hbase[(size_t)ss[u] * HC + lane * 2]);
#pragma unroll
                for (int u = 0; u < 8; u++) acc_h2(acc, hv[u], ww[u]);
            }
        }
        for (; j + 4 <= cnt; j += 4) {
            int   ss[4];
            float ww[4];
#pragma unroll
            for (int u = 0; u < 4; u++) {
                ss[u] = s_s[wp][j + u];
                ww[u] = (H == 2) ? s_w[wp][(j + u) * 2 + head] : s_w[wp][j + u];
            }
            if (VEC == 4) {
                uint2 hv[4];
#pragma unroll
                for (int u = 0; u < 4; u++)
                    hv[u] = *reinterpret_cast<const uint2*>(&hbase[(size_t)ss[u] * HC + lane * 4]);
#pragma unroll
                for (int u = 0; u < 4; u++) acc_h4(acc, hv[u].x, hv[u].y, ww[u]);
            } else {
                unsigned hv[4];
#pragma unroll
                for (int u = 0; u < 4; u++)
                    hv[u] = *reinterpret_cast<const unsigned*>(&hbase[(size_t)ss[u] * HC + lane * 2]);
#pragma unroll
                for (int u = 0; u < 4; u++) acc_h2(acc, hv[u], ww[u]);
            }
        }
        for (; j < cnt; j++) {
            int s   = s_s[wp][j];
            float w = (H == 2) ? s_w[wp][j * 2 + head] : s_w[wp][j];
            if (VEC == 4) {
                uint2 hv = *reinterpret_cast<const uint2*>(&hbase[(size_t)s * HC + lane * 4]);
                acc_h4(acc, hv.x, hv.y, w);
            } else {
                unsigned hv = *reinterpret_cast<const unsigned*>(&hbase[(size_t)s * HC + lane * 2]);
                acc_h2(acc, hv, w);
            }
        }
        __syncwarp();
    }

    // self loop: weight recomputed from alpha buffers
    float ws = expf(lrelu(g_as[node * H + head] + ((H == 2 && head) ? ad1 : ad0)));
    if (VEC == 4) {
        uint2 hv = *reinterpret_cast<const uint2*>(&hbase[(size_t)node * HC + lane * 4]);
        acc_h4(acc, hv.x, hv.y, ws);
    } else {
        unsigned hv = *reinterpret_cast<const unsigned*>(&hbase[(size_t)node * HC + lane * 2]);
        acc_h2(acc, hv, ws);
    }

#pragma unroll
    for (int o = 16; o > 0; o >>= 1) {
        d0 += __shfl_xor_sync(0xffffffffu, d0, o);
        if (H == 2) d1 += __shfl_xor_sync(0xffffffffu, d1, o);
    }
    float dh = (H == 2 && head) ? d1 : d0;
    float inv = 1.0f / (dh + ws + 1e-16f);

    float outv[VEC];
#pragma unroll
    for (int v = 0; v < VEC; v++) {
        float t = acc[v] * inv + bias[lane * VEC + v];
        if (ACT) t = t > 0.f ? t : expm1f(t);
        outv[v] = t;
    }

    if (POOL) {
        // fused mean-pool accumulation (VEC==2: lane holds cols 2*lane, 2*lane+1)
        int b = batch[node];
        float o2 = __shfl_down_sync(0xffffffffu, outv[0], 1);
        float o3 = __shfl_down_sync(0xffffffffu, outv[VEC - 1], 1);
        if ((lane & 1) == 0)
            red4(&g_pool[b * 64 + lane * 2], outv[0], outv[VEC - 1], o2, o3);
    } else {
        if (VEC == 4)
            *reinterpret_cast<float4*>(&g_x[(size_t)node * HC + lane * 4]) =
                make_float4(outv[0], outv[1], outv[2], outv[3]);
        else
            *reinterpret_cast<float2*>(&g_x[(size_t)node * HC + lane * 2]) =
                make_float2(outv[0], outv[1]);
    }
}

// =================== MLP head (counts via binary search on sorted batch) ===================
__global__ void k_mlp(const int* __restrict__ batch,
                      const float* __restrict__ obs,
                      const float* __restrict__ Ws1, const float* __restrict__ bs1,
                      const float* __restrict__ lng, const float* __restrict__ lnb,
                      const float* __restrict__ Ws2, const float* __restrict__ bs2,
                      const float* __restrict__ Wa,  const float* __restrict__ ba,
                      const float* __restrict__ Wc,  const float* __restrict__ bc,
                      float* __restrict__ out) {
    __shared__ float comb[64 + OBSD];
    __shared__ float hb[MHD];
    __shared__ float h2[MHD];
    __shared__ float rb[8];
    __shared__ float stats[2];
    __shared__ float s_cnt;

    int b = blockIdx.x;
    int tid = threadIdx.x;

    if (tid == 0) {
        int lo = 0, hi = NN;
        while (lo < hi) { int m = (lo + hi) >> 1; if (batch[m] < b) lo = m + 1; else hi = m; }
        int st = lo; lo = 0; hi = NN;
        while (lo < hi) { int m = (lo + hi) >> 1; if (batch[m] < b + 1) lo = m + 1; else hi = m; }
        s_cnt = (float)(lo - st);
    }
    __syncthreads();

    if (tid < 64)             comb[tid] = g_pool[b * 64 + tid] / fmaxf(s_cnt, 1.0f);
    else if (tid < 64 + OBSD) comb[tid] = obs[b * OBSD + (tid - 64)];
    __syncthreads();

    float s = bs1[tid];
    for (int k = 0; k < 64 + OBSD; k++) s += comb[k] * Ws1[k * MHD + tid];

    float v = s;
#pragma unroll
    for (int o = 16; o > 0; o >>= 1) v += __shfl_down_sync(0xffffffffu, v, o);
    if ((tid & 31) == 0) rb[tid >> 5] = v;
    __syncthreads();
    if (tid == 0) { float t = 0.f; for (int w = 0; w < 8; w++) t += rb[w]; stats[0] = t / MHD; }
    __syncthreads();
    float mu = stats[0];
    float dv = s - mu;
    v = dv * dv;
#pragma unroll
    for (int o = 16; o > 0; o >>= 1) v += __shfl_down_sync(0xffffffffu, v, o);
    if ((tid & 31) == 0) rb[tid >> 5] = v;
    __syncthreads();
    if (tid == 0) { float t = 0.f; for (int w = 0; w < 8; w++) t += rb[w]; stats[1] = t / MHD; }
    __syncthreads();

    float hn = dv * rsqrtf(stats[1] + 1e-5f) * lng[tid] + lnb[tid];
    hb[tid] = fmaxf(hn, 0.f);
    __syncthreads();

    float s2 = bs2[tid];
    for (int k = 0; k < MHD; k++) s2 += hb[k] * Ws2[k * MHD + tid];
    h2[tid] = fmaxf(s2, 0.f);
    __syncthreads();

    if (tid < NAD) {
        float t = ba[tid];
        for (int k = 0; k < MHD; k++) t += h2[k] * Wa[k * NAD + tid];
        out[b * NAD + tid] = t;
    }
    if (tid == NAD) {
        float t = bc[0];
        for (int k = 0; k < MHD; k++) t += h2[k] * Wc[k];
        out[BB * NAD + b] = t;
    }
}

// =================== launch ===================
static inline int gs(long long n) { return (int)((n + 255) / 256); }

extern "C" void kernel_launch(void* const* d_in, const int* in_sizes, int n_in,
                              void* d_out, int out_size) {
    const float* obs   = (const float*)d_in[0];
    const float* nf    = (const float*)d_in[1];
    const int*   ei    = (const int*)  d_in[2];
    const int*   batch = (const int*)  d_in[3];
    const float* W0 = (const float*)d_in[4];
    const float* as0 = (const float*)d_in[5];
    const float* ad0 = (const float*)d_in[6];
    const float* b0  = (const float*)d_in[7];
    const float* W1 = (const float*)d_in[8];
    const float* as1 = (const float*)d_in[9];
    const float* ad1 = (const float*)d_in[10];
    const float* b1  = (const float*)d_in[11];
    const float* W2 = (const float*)d_in[12];
    const float* as2 = (const float*)d_in[13];
    const float* ad2 = (const float*)d_in[14];
    const float* b2  = (const float*)d_in[15];
    const float* Ws1 = (const float*)d_in[16];
    const float* bs1 = (const float*)d_in[17];
    const float* lng = (const float*)d_in[18];
    const float* lnb = (const float*)d_in[19];
    const float* Ws2 = (const float*)d_in[20];
    const float* bs2 = (const float*)d_in[21];
    const float* Wa  = (const float*)d_in[22];
    const float* ba  = (const float*)d_in[23];
    const float* Wc  = (const float*)d_in[24];
    const float* bc  = (const float*)d_in[25];
    float* out = (float*)d_out;

    void *p_deg, *p_pool;
    cudaGetSymbolAddress(&p_deg,  g_deg);
    cudaGetSymbolAddress(&p_pool, g_pool);
    cudaMemsetAsync(p_deg,  0, (NN + 1) * sizeof(int));
    cudaMemsetAsync(p_pool, 0, BB * 64 * sizeof(float));

    const int AGGB = (NN + 7) / 8;  // 6250

    // 1. fused histogram + layer-0 GEMM (+alpha0)
    k_hg0<<<2 * G0B, 256>>>(ei, nf, W0, as0, ad0);
    // 2-3. scan + CSR fill
    k_scan<<<1, 1024>>>();
    k_fill<<<gs(EE / 4), 256>>>(ei);
    // 4. layer-0 aggregate
    k_agg<128, 2, true, false><<<AGGB, 256>>>(b0, nullptr);
    // 5-6. layer 1
    k_gemm128<128, 2><<<782, 256>>>(W1, as1, ad1);
    k_agg<128, 2, true, false><<<AGGB, 256>>>(b1, nullptr);
    // 7-8. layer 2 (agg fuses mean-pool)
    k_gemm128<64, 1><<<782, 256>>>(W2, as2, ad2);
    k_agg<64, 1, false, true><<<AGGB, 256>>>(b2, batch);
    // 9. MLP head
    k_mlp<<<BB, MHD>>>(batch, obs, Ws1, bs1, lng, lnb, Ws2, bs2, Wa, ba, Wc, bc, out);
}

// round 12
// speedup vs baseline: 1.0010x; 1.0010x over previous
#include <cuda_runtime.h>
#include <cuda_bf16.h>
#include <math.h>

#define NN 50000
#define EE 800000
#define BB 64
#define OBSD 128
#define MHD 256
#define NAD 16

// ---------------- scratch ----------------
__device__ float          g_x[NN * 128];
__device__ __nv_bfloat16  g_h[NN * 128];
__device__ float g_as[NN * 2];
__device__ float g_ad[NN * 2];
__device__ int   g_deg[NN + 1];
__device__ int   g_off[NN + 1];
__device__ int   g_cur[NN];
__device__ int   g_csr[EE];
__device__ float g_pool[BB * 64];

__device__ __forceinline__ float lrelu(float v) { return v > 0.f ? v : 0.2f * v; }

__device__ __forceinline__ void red4(float* p, float a, float b, float c, float d) {
    asm volatile("red.global.add.v4.f32 [%0], {%1,%2,%3,%4};"
                 :: "l"(p), "f"(a), "f"(b), "f"(c), "f"(d) : "memory");
}

// ---- packed f32x2 helpers ----
__device__ __forceinline__ unsigned long long pack2(float x, float y) {
    unsigned long long r;
    asm("mov.b64 %0, {%1, %2};" : "=l"(r) : "r"(__float_as_uint(x)), "r"(__float_as_uint(y)));
    return r;
}
__device__ __forceinline__ void unpack2(unsigned long long v, float& x, float& y) {
    unsigned lo, hi;
    asm("mov.b64 {%0, %1}, %2;" : "=r"(lo), "=r"(hi) : "l"(v));
    x = __uint_as_float(lo); y = __uint_as_float(hi);
}
__device__ __forceinline__ void fma2(unsigned long long& d, unsigned long long a, unsigned long long b) {
    asm("fma.rn.f32x2 %0, %1, %2, %0;" : "+l"(d) : "l"(a), "l"(b));
}

// bf16 helpers
__device__ __forceinline__ void st_h4(__nv_bfloat16* p, const float* f) {
    uint2 u;
    *reinterpret_cast<__nv_bfloat162*>(&u.x) = __floats2bfloat162_rn(f[0], f[1]);
    *reinterpret_cast<__nv_bfloat162*>(&u.y) = __floats2bfloat162_rn(f[2], f[3]);
    *reinterpret_cast<uint2*>(p) = u;
}
__device__ __forceinline__ void st_h2(__nv_bfloat16* p, const float* f) {
    unsigned u;
    *reinterpret_cast<__nv_bfloat162*>(&u) = __floats2bfloat162_rn(f[0], f[1]);
    *reinterpret_cast<unsigned*>(p) = u;
}
__device__ __forceinline__ void acc_h4(float* acc, unsigned ux, unsigned uy, float w) {
    float2 lo = __bfloat1622float2(*reinterpret_cast<__nv_bfloat162*>(&ux));
    float2 hi = __bfloat1622float2(*reinterpret_cast<__nv_bfloat162*>(&uy));
    acc[0] += w * lo.x; acc[1] += w * lo.y; acc[2] += w * hi.x; acc[3] += w * hi.y;
}
__device__ __forceinline__ void acc_h2(float* acc, unsigned u, float w) {
    float2 lo = __bfloat1622float2(*reinterpret_cast<__nv_bfloat162*>(&u));
    acc[0] += w * lo.x; acc[1] += w * lo.y;
}

// =================== layer-0 GEMM (FIN=8 -> HC=128), parallel in-block fold ===================
__global__ void __launch_bounds__(256) k_gemm0(const float* __restrict__ xin,
                                               const float* __restrict__ W,
                                               const float* __restrict__ asrc,
                                               const float* __restrict__ adst) {
    __shared__ float Wsh[8 * 128];
    __shared__ float wfsh[32];
    __shared__ float wred[256];
    int tid = threadIdx.x, lane = tid & 31, wp = tid >> 5;
    for (int i = tid; i < 8 * 128; i += 256) Wsh[i] = W[i];
    __syncthreads();
    {
        int d = tid >> 3, e = tid & 7;
        int a = d >> 3, k = d & 7, h = a & 1;
        const float* av = ((a < 2) ? asrc : adst) + h * 64;
        const float* wr = &Wsh[k * 128 + h * 64];
        float s = 0.f;
#pragma unroll
        for (int c = 0; c < 8; c++) s += wr[e + c * 8] * av[e + c * 8];
        wred[tid] = s;
    }
    __syncthreads();
    if (tid < 32) {
        float s = 0.f;
#pragma unroll
        for (int e = 0; e < 8; e++) s += wred[tid * 8 + e];
        wfsh[tid] = s;
    }
    __syncthreads();

    const int stride = gridDim.x * 8;
    int node = blockIdx.x * 8 + wp;
    float4 pa, pb;
    if (node < NN) {
        pa = *reinterpret_cast<const float4*>(&xin[node * 8]);
        pb = *reinterpret_cast<const float4*>(&xin[node * 8 + 4]);
    }
    while (node < NN) {
        float4 xa = pa, xb = pb;
        int nnext = node + stride;
        if (nnext < NN) {
            pa = *reinterpret_cast<const float4*>(&xin[nnext * 8]);
            pb = *reinterpret_cast<const float4*>(&xin[nnext * 8 + 4]);
        }
        float xk[8] = {xa.x, xa.y, xa.z, xa.w, xb.x, xb.y, xb.z, xb.w};
        float acc[4] = {0.f, 0.f, 0.f, 0.f};
#pragma unroll
        for (int k = 0; k < 8; k++) {
            float4 w = *reinterpret_cast<const float4*>(&Wsh[k * 128 + lane * 4]);
            acc[0] += xk[k] * w.x; acc[1] += xk[k] * w.y;
            acc[2] += xk[k] * w.z; acc[3] += xk[k] * w.w;
        }
        st_h4(&g_h[(size_t)node * 128 + lane * 4], acc);

        int a = lane & 3;
        float s = 0.f;
#pragma unroll
        for (int k = 0; k < 8; k++) s += xk[k] * wfsh[a * 8 + k];
        if (lane < 2)      g_as[node * 2 + lane] = s;
        else if (lane < 4) g_ad[node * 2 + lane - 2] = s;
        node = nnext;
    }
}

// =================== CSR build ===================
__global__ void k_hist(const int* __restrict__ ei) {
    const int4* d4 = reinterpret_cast<const int4*>(ei + EE);
    for (int i = blockIdx.x * blockDim.x + threadIdx.x; i < EE / 4; i += gridDim.x * blockDim.x) {
        int4 v = d4[i];
        atomicAdd(&g_deg[v.x], 1);
        atomicAdd(&g_deg[v.y], 1);
        atomicAdd(&g_deg[v.z], 1);
        atomicAdd(&g_deg[v.w], 1);
    }
}
__global__ void k_scan() {
    __shared__ int sh[1024];
    const int PER = 49;
    int tid = threadIdx.x;
    int base = tid * PER;
    int s = 0;
    for (int k = 0; k < PER; k++) {
        int i = base + k;
        if (i < NN) s += g_deg[i];
    }
    sh[tid] = s;
    __syncthreads();
    for (int o = 1; o < 1024; o <<= 1) {
        int t = (tid >= o) ? sh[tid - o] : 0;
        __syncthreads();
        sh[tid] += t;
        __syncthreads();
    }
    int run = sh[tid] - s;
    for (int k = 0; k < PER; k++) {
        int i = base + k;
        if (i < NN) {
            int d = g_deg[i];
            g_off[i] = run;
            g_cur[i] = run;
            run += d;
        }
    }
    if (tid == 0) g_off[NN] = EE;
}
__global__ void k_fill(const int* __restrict__ ei) {
    const int4* s4 = reinterpret_cast<const int4*>(ei);
    const int4* d4 = reinterpret_cast<const int4*>(ei + EE);
    for (int i = blockIdx.x * blockDim.x + threadIdx.x; i < EE / 4; i += gridDim.x * blockDim.x) {
        int4 s = s4[i];
        int4 d = d4[i];
        g_csr[atomicAdd(&g_cur[d.x], 1)] = s.x;
        g_csr[atomicAdd(&g_cur[d.y], 1)] = s.y;
        g_csr[atomicAdd(&g_cur[d.z], 1)] = s.z;
        g_csr[atomicAdd(&g_cur[d.w], 1)] = s.w;
    }
}

// =================== epilogue helper: alpha dots (layer 1/2 GEMM) ===================
template <int H, int VEC>
__device__ __forceinline__ void alpha_epilogue(int node, int lane, int head,
                                               const float* acc, const float* asv, const float* adv) {
    float vs = 0.f, vd = 0.f;
#pragma unroll
    for (int v = 0; v < VEC; v++) { vs += acc[v] * asv[v]; vd += acc[v] * adv[v]; }
    constexpr int RO = (H == 2) ? 8 : 16;
#pragma unroll
    for (int o = RO; o > 0; o >>= 1) {
        vs += __shfl_down_sync(0xffffffffu, vs, o);
        vd += __shfl_down_sync(0xffffffffu, vd, o);
    }
    if ((lane & ((H == 2) ? 15 : 31)) == 0) {
        g_as[node * H + head] = vs;
        g_ad[node * H + head] = vd;
    }
}

// =================== big GEMM (128 -> HC) with packed f32x2 + alpha epilogue ===================
template <int HC, int H>
__global__ void __launch_bounds__(256) k_gemm128(const float* __restrict__ W,
                                                 const float* __restrict__ asrc,
                                                 const float* __restrict__ adst) {
    constexpr int VEC = HC / 32;
    constexpr int P   = VEC / 2;
    constexpr int KT  = 32;
    constexpr int NCH = 64;
    __shared__ float Wsh[KT * HC];
    __shared__ unsigned long long xsh2[NCH * KT];
    int tid = threadIdx.x, lane = tid & 31, wp = tid >> 5;
    int head = (H == 2) ? (lane >> 4) : 0;
    float asv[VEC], adv[VEC];
#pragma unroll
    for (int v = 0; v < VEC; v++) { asv[v] = asrc[lane * VEC + v]; adv[v] = adst[lane * VEC + v]; }

    for (int base = blockIdx.x * NCH; base < NN; base += gridDim.x * NCH) {
        unsigned long long acc2[8][P];
#pragma unroll
        for (int n = 0; n < 8; n++)
#pragma unroll
            for (int p = 0; p < P; p++) acc2[n][p] = 0ull;

        for (int k0 = 0; k0 < 128; k0 += KT) {
            for (int i = tid; i < KT * HC; i += 256)
                Wsh[i] = W[((i / HC) + k0) * HC + (i % HC)];
            for (int i = tid; i < NCH * KT; i += 256) {
                int n = base + i / KT;
                float x = (n < NN) ? g_x[(size_t)n * 128 + k0 + (i % KT)] : 0.f;
                xsh2[i] = pack2(x, x);
            }
            __syncthreads();
#pragma unroll
            for (int kk = 0; kk < KT; kk += 4) {
                unsigned long long wv2[4][P];
#pragma unroll
                for (int j = 0; j < 4; j++)
#pragma unroll
                    for (int p = 0; p < P; p++)
                        wv2[j][p] = *reinterpret_cast<const unsigned long long*>(
                            &Wsh[(kk + j) * HC + lane * VEC + 2 * p]);
#pragma unroll
                for (int n = 0; n < 8; n++) {
                    ulonglong2 xa = *reinterpret_cast<const ulonglong2*>(&xsh2[(wp * 8 + n) * KT + kk]);
                    ulonglong2 xb = *reinterpret_cast<const ulonglong2*>(&xsh2[(wp * 8 + n) * KT + kk + 2]);
#pragma unroll
                    for (int p = 0; p < P; p++) {
                        fma2(acc2[n][p], xa.x, wv2[0][p]);
                        fma2(acc2[n][p], xa.y, wv2[1][p]);
                        fma2(acc2[n][p], xb.x, wv2[2][p]);
                        fma2(acc2[n][p], xb.y, wv2[3][p]);
                    }
                }
            }
            __syncthreads();
        }

#pragma unroll
        for (int n = 0; n < 8; n++) {
            int node = base + wp * 8 + n;
            if (node >= NN) break;
            float f[VEC];
#pragma unroll
            for (int p = 0; p < P; p++) unpack2(acc2[n][p], f[2 * p], f[2 * p + 1]);
            if (VEC == 4) st_h4(&g_h[(size_t)node * HC + lane * 4], f);
            else          st_h2(&g_h[(size_t)node * HC + lane * 2], f);
            alpha_epilogue<H, VEC>(node, lane, head, f, asv, adv);
        }
    }
}

// =================== fused softmax-aggregate (warp per dst node) ===================
template <int HC, int H, bool ACT, bool POOL>
__global__ void __launch_bounds__(256) k_agg(const float* __restrict__ bias,
                                             const int* __restrict__ batch) {
    constexpr int VEC = HC / 32;
    __shared__ int   s_s[8][32];
    __shared__ float s_w[8][32 * H];
    int lane = threadIdx.x & 31, wp = threadIdx.x >> 5;
    int node = blockIdx.x * 8 + wp;
    if (node >= NN) return;
    int head = (H == 2) ? (lane >> 4) : 0;

    float ad0 = g_ad[node * H];
    float ad1 = (H == 2) ? g_ad[node * H + 1] : 0.f;
    int beg = g_off[node], end = g_off[node + 1];

    float acc[VEC];
#pragma unroll
    for (int v = 0; v < VEC; v++) acc[v] = 0.f;
    float d0 = 0.f, d1 = 0.f;

    const __nv_bfloat16* __restrict__ hbase = g_h;

    for (int chunk = beg; chunk < end; chunk += 32) {
        int i = chunk + lane;
        if (i < end) {
            int s = g_csr[i];
            s_s[wp][lane] = s;
            if (H == 2) {
                float2 a = *reinterpret_cast<const float2*>(&g_as[s * 2]);
                float w0 = expf(lrelu(a.x + ad0));
                float w1 = expf(lrelu(a.y + ad1));
                d0 += w0; d1 += w1;
                s_w[wp][lane * 2]     = w0;
                s_w[wp][lane * 2 + 1] = w1;
            } else {
                float w0 = expf(lrelu(g_as[s] + ad0));
                d0 += w0;
                s_w[wp][lane] = w0;
            }
        }
        __syncwarp();
        int cnt = min(32, end - chunk);
        int j = 0;
        for (; j + 8 <= cnt; j += 8) {
            int   ss[8];
            float ww[8];
#pragma unroll
            for (int u = 0; u < 8; u++) {
                ss[u] = s_s[wp][j + u];
                ww[u] = (H == 2) ? s_w[wp][(j + u) * 2 + head] : s_w[wp][j + u];
            }
            if (VEC == 4) {
                uint2 hv[8];
#pragma unroll
                for (int u = 0; u < 8; u++)
                    hv[u] = *reinterpret_cast<const uint2*>(&hbase[(size_t)ss[u] * HC + lane * 4]);
#pragma unroll
                for (int u = 0; u < 8; u++) acc_h4(acc, hv[u].x, hv[u].y, ww[u]);
            } else {
                unsigned hv[8];
#pragma unroll
                for (int u = 0; u < 8; u++)
                    hv[u] = *reinterpret_cast<const unsigned*>(&hbase[(size_t)ss[u] * HC + lane * 2]);
#pragma unroll
                for (int u = 0; u < 8; u++) acc_h2(acc, hv[u], ww[u]);
            }
        }
        for (; j + 4 <= cnt; j += 4) {
            int   ss[4];
            float ww[4];
#pragma unroll
            for (int u = 0; u < 4; u++) {
                ss[u] = s_s[wp][j + u];
                ww[u] = (H == 2) ? s_w[wp][(j + u) * 2 + head] : s_w[wp][j + u];
            }
            if (VEC == 4) {
                uint2 hv[4];
#pragma unroll
                for (int u = 0; u < 4; u++)
                    hv[u] = *reinterpret_cast<const uint2*>(&hbase[(size_t)ss[u] * HC + lane * 4]);
#pragma unroll
                for (int u = 0; u < 4; u++) acc_h4(acc, hv[u].x, hv[u].y, ww[u]);
            } else {
                unsigned hv[4];
#pragma unroll
                for (int u = 0; u < 4; u++)
                    hv[u] = *reinterpret_cast<const unsigned*>(&hbase[(size_t)ss[u] * HC + lane * 2]);
#pragma unroll
                for (int u = 0; u < 4; u++) acc_h2(acc, hv[u], ww[u]);
            }
        }
        for (; j < cnt; j++) {
            int s   = s_s[wp][j];
            float w = (H == 2) ? s_w[wp][j * 2 + head] : s_w[wp][j];
            if (VEC == 4) {
                uint2 hv = *reinterpret_cast<const uint2*>(&hbase[(size_t)s * HC + lane * 4]);
                acc_h4(acc, hv.x, hv.y, w);
            } else {
                unsigned hv = *reinterpret_cast<const unsigned*>(&hbase[(size_t)s * HC + lane * 2]);
                acc_h2(acc, hv, w);
            }
        }
        __syncwarp();
    }

    // self loop
    float ws = expf(lrelu(g_as[node * H + head] + ((H == 2 && head) ? ad1 : ad0)));
    if (VEC == 4) {
        uint2 hv = *reinterpret_cast<const uint2*>(&hbase[(size_t)node * HC + lane * 4]);
        acc_h4(acc, hv.x, hv.y, ws);
    } else {
        unsigned hv = *reinterpret_cast<const unsigned*>(&hbase[(size_t)node * HC + lane * 2]);
        acc_h2(acc, hv, ws);
    }

#pragma unroll
    for (int o = 16; o > 0; o >>= 1) {
        d0 += __shfl_xor_sync(0xffffffffu, d0, o);
        if (H == 2) d1 += __shfl_xor_sync(0xffffffffu, d1, o);
    }
    float dh = (H == 2 && head) ? d1 : d0;
    float inv = 1.0f / (dh + ws + 1e-16f);

    float outv[VEC];
#pragma unroll
    for (int v = 0; v < VEC; v++) {
        float t = acc[v] * inv + bias[lane * VEC + v];
        if (ACT) t = t > 0.f ? t : expm1f(t);
        outv[v] = t;
    }

    if (POOL) {
        int b = batch[node];
        float o2 = __shfl_down_sync(0xffffffffu, outv[0], 1);
        float o3 = __shfl_down_sync(0xffffffffu, outv[VEC - 1], 1);
        if ((lane & 1) == 0)
            red4(&g_pool[b * 64 + lane * 2], outv[0], outv[VEC - 1], o2, o3);
    } else {
        if (VEC == 4)
            *reinterpret_cast<float4*>(&g_x[(size_t)node * HC + lane * 4]) =
                make_float4(outv[0], outv[1], outv[2], outv[3]);
        else
            *reinterpret_cast<float2*>(&g_x[(size_t)node * HC + lane * 2]) =
                make_float2(outv[0], outv[1]);
    }
}

// =================== MLP head (counts via binary search on sorted batch) ===================
__global__ void k_mlp(const int* __restrict__ batch,
                      const float* __restrict__ obs,
                      const float* __restrict__ Ws1, const float* __restrict__ bs1,
                      const float* __restrict__ lng, const float* __restrict__ lnb,
                      const float* __restrict__ Ws2, const float* __restrict__ bs2,
                      const float* __restrict__ Wa,  const float* __restrict__ ba,
                      const float* __restrict__ Wc,  const float* __restrict__ bc,
                      float* __restrict__ out) {
    __shared__ float comb[64 + OBSD];
    __shared__ float hb[MHD];
    __shared__ float h2[MHD];
    __shared__ float rb[8];
    __shared__ float stats[2];
    __shared__ float s_cnt;

    int b = blockIdx.x;
    int tid = threadIdx.x;

    if (tid == 0) {
        int lo = 0, hi = NN;
        while (lo < hi) { int m = (lo + hi) >> 1; if (batch[m] < b) lo = m + 1; else hi = m; }
        int st = lo; lo = 0; hi = NN;
        while (lo < hi) { int m = (lo + hi) >> 1; if (batch[m] < b + 1) lo = m + 1; else hi = m; }
        s_cnt = (float)(lo - st);
    }
    __syncthreads();

    if (tid < 64)             comb[tid] = g_pool[b * 64 + tid] / fmaxf(s_cnt, 1.0f);
    else if (tid < 64 + OBSD) comb[tid] = obs[b * OBSD + (tid - 64)];
    __syncthreads();

    float s = bs1[tid];
    for (int k = 0; k < 64 + OBSD; k++) s += comb[k] * Ws1[k * MHD + tid];

    float v = s;
#pragma unroll
    for (int o = 16; o > 0; o >>= 1) v += __shfl_down_sync(0xffffffffu, v, o);
    if ((tid & 31) == 0) rb[tid >> 5] = v;
    __syncthreads();
    if (tid == 0) { float t = 0.f; for (int w = 0; w < 8; w++) t += rb[w]; stats[0] = t / MHD; }
    __syncthreads();
    float mu = stats[0];
    float dv = s - mu;
    v = dv * dv;
#pragma unroll
    for (int o = 16; o > 0; o >>= 1) v += __shfl_down_sync(0xffffffffu, v, o);
    if ((tid & 31) == 0) rb[tid >> 5] = v;
    __syncthreads();
    if (tid == 0) { float t = 0.f; for (int w = 0; w < 8; w++) t += rb[w]; stats[1] = t / MHD; }
    __syncthreads();

    float hn = dv * rsqrtf(stats[1] + 1e-5f) * lng[tid] + lnb[tid];
    hb[tid] = fmaxf(hn, 0.f);
    __syncthreads();

    float s2 = bs2[tid];
    for (int k = 0; k < MHD; k++) s2 += hb[k] * Ws2[k * MHD + tid];
    h2[tid] = fmaxf(s2, 0.f);
    __syncthreads();

    if (tid < NAD) {
        float t = ba[tid];
        for (int k = 0; k < MHD; k++) t += h2[k] * Wa[k * NAD + tid];
        out[b * NAD + tid] = t;
    }
    if (tid == NAD) {
        float t = bc[0];
        for (int k = 0; k < MHD; k++) t += h2[k] * Wc[k];
        out[BB * NAD + b] = t;
    }
}

// =================== launch ===================
static inline int gs(long long n) { return (int)((n + 255) / 256); }

extern "C" void kernel_launch(void* const* d_in, const int* in_sizes, int n_in,
                              void* d_out, int out_size) {
    const float* obs   = (const float*)d_in[0];
    const float* nf    = (const float*)d_in[1];
    const int*   ei    = (const int*)  d_in[2];
    const int*   batch = (const int*)  d_in[3];
    const float* W0 = (const float*)d_in[4];
    const float* as0 = (const float*)d_in[5];
    const float* ad0 = (const float*)d_in[6];
    const float* b0  = (const float*)d_in[7];
    const float* W1 = (const float*)d_in[8];
    const float* as1 = (const float*)d_in[9];
    const float* ad1 = (const float*)d_in[10];
    const float* b1  = (const float*)d_in[11];
    const float* W2 = (const float*)d_in[12];
    const float* as2 = (const float*)d_in[13];
    const float* ad2 = (const float*)d_in[14];
    const float* b2  = (const float*)d_in[15];
    const float* Ws1 = (const float*)d_in[16];
    const float* bs1 = (const float*)d_in[17];
    const float* lng = (const float*)d_in[18];
    const float* lnb = (const float*)d_in[19];
    const float* Ws2 = (const float*)d_in[20];
    const float* bs2 = (const float*)d_in[21];
    const float* Wa  = (const float*)d_in[22];
    const float* ba  = (const float*)d_in[23];
    const float* Wc  = (const float*)d_in[24];
    const float* bc  = (const float*)d_in[25];
    float* out = (float*)d_out;

    void *p_deg, *p_pool;
    cudaGetSymbolAddress(&p_deg,  g_deg);
    cudaGetSymbolAddress(&p_pool, g_pool);

    // fork a side stream: gemm0 runs concurrently with CSR build (independent)
    cudaStream_t s2;
    cudaEvent_t evF, evJ;
    cudaStreamCreateWithFlags(&s2, cudaStreamNonBlocking);
    cudaEventCreateWithFlags(&evF, cudaEventDisableTiming);
    cudaEventCreateWithFlags(&evJ, cudaEventDisableTiming);

    cudaMemsetAsync(p_deg,  0, (NN + 1) * sizeof(int));
    cudaMemsetAsync(p_pool, 0, BB * 64 * sizeof(float));

    cudaEventRecord(evF, 0);
    cudaStreamWaitEvent(s2, evF, 0);
    k_gemm0<<<782, 256, 0, s2>>>(nf, W0, as0, ad0);     // side stream

    k_hist<<<gs(EE / 4), 256>>>(ei);                     // main stream: CSR chain
    k_scan<<<1, 1024>>>();
    k_fill<<<gs(EE / 4), 256>>>(ei);

    cudaEventRecord(evJ, s2);
    cudaStreamWaitEvent(0, evJ, 0);                      // join before agg0

    const int AGGB = (NN + 7) / 8;  // 6250

    k_agg<128, 2, true, false><<<AGGB, 256>>>(b0, nullptr);
    k_gemm128<128, 2><<<782, 256>>>(W1, as1, ad1);
    k_agg<128, 2, true, false><<<AGGB, 256>>>(b1, nullptr);
    k_gemm128<64, 1><<<782, 256>>>(W2, as2, ad2);
    k_agg<64, 1, false, true><<<AGGB, 256>>>(b2, batch);
    k_mlp<<<BB, MHD>>>(batch, obs, Ws1, bs1, lng, lnb, Ws2, bs2, Wa, ba, Wc, bc, out);
}

// round 13
// speedup vs baseline: 1.0070x; 1.0059x over previous
#include <cuda_runtime.h>
#include <cuda_bf16.h>
#include <math.h>

#define NN 50000
#define EE 800000
#define BB 64
#define OBSD 128
#define MHD 256
#define NAD 16

// ---------------- scratch ----------------
__device__ float          g_x[NN * 128];
__device__ __nv_bfloat16  g_h[NN * 128];
__device__ float g_as[NN * 2];
__device__ float g_ad[NN * 2];
__device__ int   g_deg[NN + 1];
__device__ int   g_off[NN + 1];
__device__ int   g_cur[NN];
__device__ int   g_csr[EE];
__device__ float g_pool[BB * 64];

__device__ __forceinline__ float lrelu(float v) { return v > 0.f ? v : 0.2f * v; }

__device__ __forceinline__ void red4(float* p, float a, float b, float c, float d) {
    asm volatile("red.global.add.v4.f32 [%0], {%1,%2,%3,%4};"
                 :: "l"(p), "f"(a), "f"(b), "f"(c), "f"(d) : "memory");
}

// ---- packed 64-bit helpers ----
__device__ __forceinline__ unsigned long long pack2(float x, float y) {
    unsigned long long r;
    asm("mov.b64 %0, {%1, %2};" : "=l"(r) : "r"(__float_as_uint(x)), "r"(__float_as_uint(y)));
    return r;
}
__device__ __forceinline__ unsigned long long pack2u(unsigned x, float y) {
    unsigned long long r;
    asm("mov.b64 %0, {%1, %2};" : "=l"(r) : "r"(x), "r"(__float_as_uint(y)));
    return r;
}
__device__ __forceinline__ void unpack2u(unsigned long long v, unsigned& x, float& y) {
    unsigned lo, hi;
    asm("mov.b64 {%0, %1}, %2;" : "=r"(lo), "=r"(hi) : "l"(v));
    x = lo; y = __uint_as_float(hi);
}
__device__ __forceinline__ void unpack2(unsigned long long v, float& x, float& y) {
    unsigned lo, hi;
    asm("mov.b64 {%0, %1}, %2;" : "=r"(lo), "=r"(hi) : "l"(v));
    x = __uint_as_float(lo); y = __uint_as_float(hi);
}
__device__ __forceinline__ void fma2(unsigned long long& d, unsigned long long a, unsigned long long b) {
    asm("fma.rn.f32x2 %0, %1, %2, %0;" : "+l"(d) : "l"(a), "l"(b));
}

// bf16 helpers
__device__ __forceinline__ void st_h4(__nv_bfloat16* p, const float* f) {
    uint2 u;
    *reinterpret_cast<__nv_bfloat162*>(&u.x) = __floats2bfloat162_rn(f[0], f[1]);
    *reinterpret_cast<__nv_bfloat162*>(&u.y) = __floats2bfloat162_rn(f[2], f[3]);
    *reinterpret_cast<uint2*>(p) = u;
}
__device__ __forceinline__ void st_h2(__nv_bfloat16* p, const float* f) {
    unsigned u;
    *reinterpret_cast<__nv_bfloat162*>(&u) = __floats2bfloat162_rn(f[0], f[1]);
    *reinterpret_cast<unsigned*>(p) = u;
}
__device__ __forceinline__ void acc_h4(float* acc, unsigned ux, unsigned uy, float w) {
    float2 lo = __bfloat1622float2(*reinterpret_cast<__nv_bfloat162*>(&ux));
    float2 hi = __bfloat1622float2(*reinterpret_cast<__nv_bfloat162*>(&uy));
    acc[0] += w * lo.x; acc[1] += w * lo.y; acc[2] += w * hi.x; acc[3] += w * hi.y;
}
__device__ __forceinline__ void acc_h2(float* acc, unsigned u, float w) {
    float2 lo = __bfloat1622float2(*reinterpret_cast<__nv_bfloat162*>(&u));
    acc[0] += w * lo.x; acc[1] += w * lo.y;
}

// =================== layer-0 GEMM (FIN=8 -> HC=128), parallel in-block fold ===================
__global__ void __launch_bounds__(256) k_gemm0(const float* __restrict__ xin,
                                               const float* __restrict__ W,
                                               const float* __restrict__ asrc,
                                               const float* __restrict__ adst) {
    __shared__ float Wsh[8 * 128];
    __shared__ float wfsh[32];
    __shared__ float wred[256];
    int tid = threadIdx.x, lane = tid & 31, wp = tid >> 5;
    for (int i = tid; i < 8 * 128; i += 256) Wsh[i] = W[i];
    __syncthreads();
    {
        int d = tid >> 3, e = tid & 7;
        int a = d >> 3, k = d & 7, h = a & 1;
        const float* av = ((a < 2) ? asrc : adst) + h * 64;
        const float* wr = &Wsh[k * 128 + h * 64];
        float s = 0.f;
#pragma unroll
        for (int c = 0; c < 8; c++) s += wr[e + c * 8] * av[e + c * 8];
        wred[tid] = s;
    }
    __syncthreads();
    if (tid < 32) {
        float s = 0.f;
#pragma unroll
        for (int e = 0; e < 8; e++) s += wred[tid * 8 + e];
        wfsh[tid] = s;
    }
    __syncthreads();

    const int stride = gridDim.x * 8;
    int node = blockIdx.x * 8 + wp;
    float4 pa, pb;
    if (node < NN) {
        pa = *reinterpret_cast<const float4*>(&xin[node * 8]);
        pb = *reinterpret_cast<const float4*>(&xin[node * 8 + 4]);
    }
    while (node < NN) {
        float4 xa = pa, xb = pb;
        int nnext = node + stride;
        if (nnext < NN) {
            pa = *reinterpret_cast<const float4*>(&xin[nnext * 8]);
            pb = *reinterpret_cast<const float4*>(&xin[nnext * 8 + 4]);
        }
        float xk[8] = {xa.x, xa.y, xa.z, xa.w, xb.x, xb.y, xb.z, xb.w};
        float acc[4] = {0.f, 0.f, 0.f, 0.f};
#pragma unroll
        for (int k = 0; k < 8; k++) {
            float4 w = *reinterpret_cast<const float4*>(&Wsh[k * 128 + lane * 4]);
            acc[0] += xk[k] * w.x; acc[1] += xk[k] * w.y;
            acc[2] += xk[k] * w.z; acc[3] += xk[k] * w.w;
        }
        st_h4(&g_h[(size_t)node * 128 + lane * 4], acc);

        int a = lane & 3;
        float s = 0.f;
#pragma unroll
        for (int k = 0; k < 8; k++) s += xk[k] * wfsh[a * 8 + k];
        if (lane < 2)      g_as[node * 2 + lane] = s;
        else if (lane < 4) g_ad[node * 2 + lane - 2] = s;
        node = nnext;
    }
}

// =================== CSR build (2x int4 ILP) ===================
__global__ void k_hist(const int* __restrict__ ei) {
    const int4* d4 = reinterpret_cast<const int4*>(ei + EE);
    for (int i = blockIdx.x * blockDim.x + threadIdx.x; i < EE / 8; i += gridDim.x * blockDim.x) {
        int4 a = d4[i * 2];
        int4 b = d4[i * 2 + 1];
        atomicAdd(&g_deg[a.x], 1);
        atomicAdd(&g_deg[a.y], 1);
        atomicAdd(&g_deg[a.z], 1);
        atomicAdd(&g_deg[a.w], 1);
        atomicAdd(&g_deg[b.x], 1);
        atomicAdd(&g_deg[b.y], 1);
        atomicAdd(&g_deg[b.z], 1);
        atomicAdd(&g_deg[b.w], 1);
    }
}
__global__ void k_scan() {
    __shared__ int sh[1024];
    const int PER = 49;
    int tid = threadIdx.x;
    int base = tid * PER;
    int s = 0;
    for (int k = 0; k < PER; k++) {
        int i = base + k;
        if (i < NN) s += g_deg[i];
    }
    sh[tid] = s;
    __syncthreads();
    for (int o = 1; o < 1024; o <<= 1) {
        int t = (tid >= o) ? sh[tid - o] : 0;
        __syncthreads();
        sh[tid] += t;
        __syncthreads();
    }
    int run = sh[tid] - s;
    for (int k = 0; k < PER; k++) {
        int i = base + k;
        if (i < NN) {
            int d = g_deg[i];
            g_off[i] = run;
            g_cur[i] = run;
            run += d;
        }
    }
    if (tid == 0) g_off[NN] = EE;
}
__global__ void k_fill(const int* __restrict__ ei) {
    const int4* s4 = reinterpret_cast<const int4*>(ei);
    const int4* d4 = reinterpret_cast<const int4*>(ei + EE);
    for (int i = blockIdx.x * blockDim.x + threadIdx.x; i < EE / 8; i += gridDim.x * blockDim.x) {
        int4 sa = s4[i * 2];
        int4 da = d4[i * 2];
        int4 sb = s4[i * 2 + 1];
        int4 db = d4[i * 2 + 1];
        int pa0 = atomicAdd(&g_cur[da.x], 1);
        int pa1 = atomicAdd(&g_cur[da.y], 1);
        int pa2 = atomicAdd(&g_cur[da.z], 1);
        int pa3 = atomicAdd(&g_cur[da.w], 1);
        int pb0 = atomicAdd(&g_cur[db.x], 1);
        int pb1 = atomicAdd(&g_cur[db.y], 1);
        int pb2 = atomicAdd(&g_cur[db.z], 1);
        int pb3 = atomicAdd(&g_cur[db.w], 1);
        g_csr[pa0] = sa.x; g_csr[pa1] = sa.y; g_csr[pa2] = sa.z; g_csr[pa3] = sa.w;
        g_csr[pb0] = sb.x; g_csr[pb1] = sb.y; g_csr[pb2] = sb.z; g_csr[pb3] = sb.w;
    }
}

// =================== epilogue helper: alpha dots (layer 1/2 GEMM) ===================
template <int H, int VEC>
__device__ __forceinline__ void alpha_epilogue(int node, int lane, int head,
                                               const float* acc, const float* asv, const float* adv) {
    float vs = 0.f, vd = 0.f;
#pragma unroll
    for (int v = 0; v < VEC; v++) { vs += acc[v] * asv[v]; vd += acc[v] * adv[v]; }
    constexpr int RO = (H == 2) ? 8 : 16;
#pragma unroll
    for (int o = RO; o > 0; o >>= 1) {
        vs += __shfl_down_sync(0xffffffffu, vs, o);
        vd += __shfl_down_sync(0xffffffffu, vd, o);
    }
    if ((lane & ((H == 2) ? 15 : 31)) == 0) {
        g_as[node * H + head] = vs;
        g_ad[node * H + head] = vd;
    }
}

// =================== big GEMM (128 -> HC) with packed f32x2 + alpha epilogue ===================
template <int HC, int H>
__global__ void __launch_bounds__(256) k_gemm128(const float* __restrict__ W,
                                                 const float* __restrict__ asrc,
                                                 const float* __restrict__ adst) {
    constexpr int VEC = HC / 32;
    constexpr int P   = VEC / 2;
    constexpr int KT  = 32;
    constexpr int NCH = 64;
    __shared__ float Wsh[KT * HC];
    __shared__ unsigned long long xsh2[NCH * KT];
    int tid = threadIdx.x, lane = tid & 31, wp = tid >> 5;
    int head = (H == 2) ? (lane >> 4) : 0;
    float asv[VEC], adv[VEC];
#pragma unroll
    for (int v = 0; v < VEC; v++) { asv[v] = asrc[lane * VEC + v]; adv[v] = adst[lane * VEC + v]; }

    for (int base = blockIdx.x * NCH; base < NN; base += gridDim.x * NCH) {
        unsigned long long acc2[8][P];
#pragma unroll
        for (int n = 0; n < 8; n++)
#pragma unroll
            for (int p = 0; p < P; p++) acc2[n][p] = 0ull;

        for (int k0 = 0; k0 < 128; k0 += KT) {
            for (int i = tid; i < KT * HC; i += 256)
                Wsh[i] = W[((i / HC) + k0) * HC + (i % HC)];
            for (int i = tid; i < NCH * KT; i += 256) {
                int n = base + i / KT;
                float x = (n < NN) ? g_x[(size_t)n * 128 + k0 + (i % KT)] : 0.f;
                xsh2[i] = pack2(x, x);
            }
            __syncthreads();
#pragma unroll
            for (int kk = 0; kk < KT; kk += 4) {
                unsigned long long wv2[4][P];
#pragma unroll
                for (int j = 0; j < 4; j++)
#pragma unroll
                    for (int p = 0; p < P; p++)
                        wv2[j][p] = *reinterpret_cast<const unsigned long long*>(
                            &Wsh[(kk + j) * HC + lane * VEC + 2 * p]);
#pragma unroll
                for (int n = 0; n < 8; n++) {
                    ulonglong2 xa = *reinterpret_cast<const ulonglong2*>(&xsh2[(wp * 8 + n) * KT + kk]);
                    ulonglong2 xb = *reinterpret_cast<const ulonglong2*>(&xsh2[(wp * 8 + n) * KT + kk + 2]);
#pragma unroll
                    for (int p = 0; p < P; p++) {
                        fma2(acc2[n][p], xa.x, wv2[0][p]);
                        fma2(acc2[n][p], xa.y, wv2[1][p]);
                        fma2(acc2[n][p], xb.x, wv2[2][p]);
                        fma2(acc2[n][p], xb.y, wv2[3][p]);
                    }
                }
            }
            __syncthreads();
        }

#pragma unroll
        for (int n = 0; n < 8; n++) {
            int node = base + wp * 8 + n;
            if (node >= NN) break;
            float f[VEC];
#pragma unroll
            for (int p = 0; p < P; p++) unpack2(acc2[n][p], f[2 * p], f[2 * p + 1]);
            if (VEC == 4) st_h4(&g_h[(size_t)node * HC + lane * 4], f);
            else          st_h2(&g_h[(size_t)node * HC + lane * 2], f);
            alpha_epilogue<H, VEC>(node, lane, head, f, asv, adv);
        }
    }
}

// =================== fused softmax-aggregate (packed 64-bit gather records) ===================
template <int HC, int H, bool ACT, bool POOL>
__global__ void __launch_bounds__(256) k_agg(const float* __restrict__ bias,
                                             const int* __restrict__ batch) {
    constexpr int VEC = HC / 32;
    constexpr int ROWB = HC * 2;          // bytes per h row
    __shared__ __align__(16) unsigned long long s_rec[8][32 * H];
    int lane = threadIdx.x & 31, wp = threadIdx.x >> 5;
    int node = blockIdx.x * 8 + wp;
    if (node >= NN) return;
    int head = (H == 2) ? (lane >> 4) : 0;

    float ad0 = g_ad[node * H];
    float ad1 = (H == 2) ? g_ad[node * H + 1] : 0.f;
    int beg = g_off[node], end = g_off[node + 1];

    float acc[VEC];
#pragma unroll
    for (int v = 0; v < VEC; v++) acc[v] = 0.f;
    float d0 = 0.f, d1 = 0.f;

    // per-lane base pointer into g_h (lane covers bytes [lane*8, lane*8+8) of each row for VEC=4)
    const char* hb_lane = reinterpret_cast<const char*>(g_h) + lane * ((VEC == 4) ? 8 : 4);

    for (int chunk = beg; chunk < end; chunk += 32) {
        int i = chunk + lane;
        if (i < end) {
            int s = g_csr[i];
            unsigned soff = (unsigned)s * ROWB;
            if (H == 2) {
                float2 a = *reinterpret_cast<const float2*>(&g_as[s * 2]);
                float w0 = expf(lrelu(a.x + ad0));
                float w1 = expf(lrelu(a.y + ad1));
                d0 += w0; d1 += w1;
                *reinterpret_cast<ulonglong2*>(&s_rec[wp][lane * 2]) =
                    make_ulonglong2(pack2u(soff, w0), pack2u(soff, w1));
            } else {
                float w0 = expf(lrelu(g_as[s] + ad0));
                d0 += w0;
                s_rec[wp][lane] = pack2u(soff, w0);
            }
        }
        __syncwarp();
        int cnt = min(32, end - chunk);
        int j = 0;
        for (; j + 8 <= cnt; j += 8) {
            unsigned soff[8];
            float    ww[8];
#pragma unroll
            for (int u = 0; u < 8; u++) {
                unsigned long long rec = (H == 2) ? s_rec[wp][(j + u) * 2 + head]
                                                  : s_rec[wp][j + u];
                unpack2u(rec, soff[u], ww[u]);
            }
            if (VEC == 4) {
                uint2 hv[8];
#pragma unroll
                for (int u = 0; u < 8; u++)
                    hv[u] = *reinterpret_cast<const uint2*>(hb_lane + soff[u]);
#pragma unroll
                for (int u = 0; u < 8; u++) acc_h4(acc, hv[u].x, hv[u].y, ww[u]);
            } else {
                unsigned hv[8];
#pragma unroll
                for (int u = 0; u < 8; u++)
                    hv[u] = *reinterpret_cast<const unsigned*>(hb_lane + soff[u]);
#pragma unroll
                for (int u = 0; u < 8; u++) acc_h2(acc, hv[u], ww[u]);
            }
        }
        for (; j + 4 <= cnt; j += 4) {
            unsigned soff[4];
            float    ww[4];
#pragma unroll
            for (int u = 0; u < 4; u++) {
                unsigned long long rec = (H == 2) ? s_rec[wp][(j + u) * 2 + head]
                                                  : s_rec[wp][j + u];
                unpack2u(rec, soff[u], ww[u]);
            }
            if (VEC == 4) {
                uint2 hv[4];
#pragma unroll
                for (int u = 0; u < 4; u++)
                    hv[u] = *reinterpret_cast<const uint2*>(hb_lane + soff[u]);
#pragma unroll
                for (int u = 0; u < 4; u++) acc_h4(acc, hv[u].x, hv[u].y, ww[u]);
            } else {
                unsigned hv[4];
#pragma unroll
                for (int u = 0; u < 4; u++)
                    hv[u] = *reinterpret_cast<const unsigned*>(hb_lane + soff[u]);
#pragma unroll
                for (int u = 0; u < 4; u++) acc_h2(acc, hv[u], ww[u]);
            }
        }
        for (; j < cnt; j++) {
            unsigned long long rec = (H == 2) ? s_rec[wp][j * 2 + head] : s_rec[wp][j];
            unsigned soff; float w;
            unpack2u(rec, soff, w);
            if (VEC == 4) {
                uint2 hv = *reinterpret_cast<const uint2*>(hb_lane + soff);
                acc_h4(acc, hv.x, hv.y, w);
            } else {
                unsigned hv = *reinterpret_cast<const unsigned*>(hb_lane + soff);
                acc_h2(acc, hv, w);
            }
        }
        __syncwarp();
    }

    // self loop
    float ws = expf(lrelu(g_as[node * H + head] + ((H == 2 && head) ? ad1 : ad0)));
    {
        unsigned soff = (unsigned)node * ROWB;
        if (VEC == 4) {
            uint2 hv = *reinterpret_cast<const uint2*>(hb_lane + soff);
            acc_h4(acc, hv.x, hv.y, ws);
        } else {
            unsigned hv = *reinterpret_cast<const unsigned*>(hb_lane + soff);
            acc_h2(acc, hv, ws);
        }
    }

#pragma unroll
    for (int o = 16; o > 0; o >>= 1) {
        d0 += __shfl_xor_sync(0xffffffffu, d0, o);
        if (H == 2) d1 += __shfl_xor_sync(0xffffffffu, d1, o);
    }
    float dh = (H == 2 && head) ? d1 : d0;
    float inv = 1.0f / (dh + ws + 1e-16f);

    float outv[VEC];
#pragma unroll
    for (int v = 0; v < VEC; v++) {
        float t = acc[v] * inv + bias[lane * VEC + v];
        if (ACT) t = t > 0.f ? t : expm1f(t);
        outv[v] = t;
    }

    if (POOL) {
        int b = batch[node];
        float o2 = __shfl_down_sync(0xffffffffu, outv[0], 1);
        float o3 = __shfl_down_sync(0xffffffffu, outv[VEC - 1], 1);
        if ((lane & 1) == 0)
            red4(&g_pool[b * 64 + lane * 2], outv[0], outv[VEC - 1], o2, o3);
    } else {
        if (VEC == 4)
            *reinterpret_cast<float4*>(&g_x[(size_t)node * HC + lane * 4]) =
                make_float4(outv[0], outv[1], outv[2], outv[3]);
        else
            *reinterpret_cast<float2*>(&g_x[(size_t)node * HC + lane * 2]) =
                make_float2(outv[0], outv[1]);
    }
}

// =================== MLP head (counts via binary search on sorted batch) ===================
__global__ void k_mlp(const int* __restrict__ batch,
                      const float* __restrict__ obs,
                      const float* __restrict__ Ws1, const float* __restrict__ bs1,
                      const float* __restrict__ lng, const float* __restrict__ lnb,
                      const float* __restrict__ Ws2, const float* __restrict__ bs2,
                      const float* __restrict__ Wa,  const float* __restrict__ ba,
                      const float* __restrict__ Wc,  const float* __restrict__ bc,
                      float* __restrict__ out) {
    __shared__ float comb[64 + OBSD];
    __shared__ float hb[MHD];
    __shared__ float h2[MHD];
    __shared__ float rb[8];
    __shared__ float stats[2];
    __shared__ float s_cnt;

    int b = blockIdx.x;
    int tid = threadIdx.x;

    if (tid == 0) {
        int lo = 0, hi = NN;
        while (lo < hi) { int m = (lo + hi) >> 1; if (batch[m] < b) lo = m + 1; else hi = m; }
        int st = lo; lo = 0; hi = NN;
        while (lo < hi) { int m = (lo + hi) >> 1; if (batch[m] < b + 1) lo = m + 1; else hi = m; }
        s_cnt = (float)(lo - st);
    }
    __syncthreads();

    if (tid < 64)             comb[tid] = g_pool[b * 64 + tid] / fmaxf(s_cnt, 1.0f);
    else if (tid < 64 + OBSD) comb[tid] = obs[b * OBSD + (tid - 64)];
    __syncthreads();

    float s = bs1[tid];
    for (int k = 0; k < 64 + OBSD; k++) s += comb[k] * Ws1[k * MHD + tid];

    float v = s;
#pragma unroll
    for (int o = 16; o > 0; o >>= 1) v += __shfl_down_sync(0xffffffffu, v, o);
    if ((tid & 31) == 0) rb[tid >> 5] = v;
    __syncthreads();
    if (tid == 0) { float t = 0.f; for (int w = 0; w < 8; w++) t += rb[w]; stats[0] = t / MHD; }
    __syncthreads();
    float mu = stats[0];
    float dv = s - mu;
    v = dv * dv;
#pragma unroll
    for (int o = 16; o > 0; o >>= 1) v += __shfl_down_sync(0xffffffffu, v, o);
    if ((tid & 31) == 0) rb[tid >> 5] = v;
    __syncthreads();
    if (tid == 0) { float t = 0.f; for (int w = 0; w < 8; w++) t += rb[w]; stats[1] = t / MHD; }
    __syncthreads();

    float hn = dv * rsqrtf(stats[1] + 1e-5f) * lng[tid] + lnb[tid];
    hb[tid] = fmaxf(hn, 0.f);
    __syncthreads();

    float s2 = bs2[tid];
    for (int k = 0; k < MHD; k++) s2 += hb[k] * Ws2[k * MHD + tid];
    h2[tid] = fmaxf(s2, 0.f);
    __syncthreads();

    if (tid < NAD) {
        float t = ba[tid];
        for (int k = 0; k < MHD; k++) t += h2[k] * Wa[k * NAD + tid];
        out[b * NAD + tid] = t;
    }
    if (tid == NAD) {
        float t = bc[0];
        for (int k = 0; k < MHD; k++) t += h2[k] * Wc[k];
        out[BB * NAD + b] = t;
    }
}

// =================== launch ===================
static inline int gs(long long n) { return (int)((n + 255) / 256); }

extern "C" void kernel_launch(void* const* d_in, const int* in_sizes, int n_in,
                              void* d_out, int out_size) {
    const float* obs   = (const float*)d_in[0];
    const float* nf    = (const float*)d_in[1];
    const int*   ei    = (const int*)  d_in[2];
    const int*   batch = (const int*)  d_in[3];
    const float* W0 = (const float*)d_in[4];
    const float* as0 = (const float*)d_in[5];
    const float* ad0 = (const float*)d_in[6];
    const float* b0  = (const float*)d_in[7];
    const float* W1 = (const float*)d_in[8];
    const float* as1 = (const float*)d_in[9];
    const float* ad1 = (const float*)d_in[10];
    const float* b1  = (const float*)d_in[11];
    const float* W2 = (const float*)d_in[12];
    const float* as2 = (const float*)d_in[13];
    const float* ad2 = (const float*)d_in[14];
    const float* b2  = (const float*)d_in[15];
    const float* Ws1 = (const float*)d_in[16];
    const float* bs1 = (const float*)d_in[17];
    const float* lng = (const float*)d_in[18];
    const float* lnb = (const float*)d_in[19];
    const float* Ws2 = (const float*)d_in[20];
    const float* bs2 = (const float*)d_in[21];
    const float* Wa  = (const float*)d_in[22];
    const float* ba  = (const float*)d_in[23];
    const float* Wc  = (const float*)d_in[24];
    const float* bc  = (const float*)d_in[25];
    float* out = (float*)d_out;

    void *p_deg, *p_pool;
    cudaGetSymbolAddress(&p_deg,  g_deg);
    cudaGetSymbolAddress(&p_pool, g_pool);

    // fork a side stream: gemm0 runs concurrently with CSR build (independent)
    cudaStream_t s2;
    cudaEvent_t evF, evJ;
    cudaStreamCreateWithFlags(&s2, cudaStreamNonBlocking);
    cudaEventCreateWithFlags(&evF, cudaEventDisableTiming);
    cudaEventCreateWithFlags(&evJ, cudaEventDisableTiming);

    cudaMemsetAsync(p_deg,  0, (NN + 1) * sizeof(int));
    cudaMemsetAsync(p_pool, 0, BB * 64 * sizeof(float));

    cudaEventRecord(evF, 0);
    cudaStreamWaitEvent(s2, evF, 0);
    k_gemm0<<<782, 256, 0, s2>>>(nf, W0, as0, ad0);     // side stream

    k_hist<<<gs(EE / 8), 256>>>(ei);                     // main stream: CSR chain
    k_scan<<<1, 1024>>>();
    k_fill<<<gs(EE / 8), 256>>>(ei);

    cudaEventRecord(evJ, s2);
    cudaStreamWaitEvent(0, evJ, 0);                      // join before agg0

    const int AGGB = (NN + 7) / 8;  // 6250

    k_agg<128, 2, true, false><<<AGGB, 256>>>(b0, nullptr);
    k_gemm128<128, 2><<<782, 256>>>(W1, as1, ad1);
    k_agg<128, 2, true, false><<<AGGB, 256>>>(b1, nullptr);
    k_gemm128<64, 1><<<782, 256>>>(W2, as2, ad2);
    k_agg<64, 1, false, true><<<AGGB, 256>>>(b2, batch);
    k_mlp<<<BB, MHD>>>(batch, obs, Ws1, bs1, lng, lnb, Ws2, bs2, Wa, ba, Wc, bc, out);
}

// round 14
// speedup vs baseline: 1.1323x; 1.1244x over previous
#include <cuda_runtime.h>
#include <cuda_bf16.h>
#include <mma.h>
#include <math.h>

#define NN 50000
#define EE 800000
#define BB 64
#define OBSD 128
#define MHD 256
#define NAD 16

using namespace nvcuda;

// ---------------- scratch ----------------
__device__ float          g_x[NN * 128];
__device__ __nv_bfloat16  g_h[NN * 128];
__device__ float g_as[NN * 2];
__device__ float g_ad[NN * 2];
__device__ int   g_deg[NN + 1];
__device__ int   g_off[NN + 1];
__device__ int   g_cur[NN];
__device__ int   g_csr[EE];
__device__ float g_pool[BB * 64];

__device__ __forceinline__ float lrelu(float v) { return v > 0.f ? v : 0.2f * v; }

__device__ __forceinline__ void red4(float* p, float a, float b, float c, float d) {
    asm volatile("red.global.add.v4.f32 [%0], {%1,%2,%3,%4};"
                 :: "l"(p), "f"(a), "f"(b), "f"(c), "f"(d) : "memory");
}

// ---- packed 64-bit helpers ----
__device__ __forceinline__ unsigned long long pack2u(unsigned x, float y) {
    unsigned long long r;
    asm("mov.b64 %0, {%1, %2};" : "=l"(r) : "r"(x), "r"(__float_as_uint(y)));
    return r;
}
__device__ __forceinline__ void unpack2u(unsigned long long v, unsigned& x, float& y) {
    unsigned lo, hi;
    asm("mov.b64 {%0, %1}, %2;" : "=r"(lo), "=r"(hi) : "l"(v));
    x = lo; y = __uint_as_float(hi);
}

// bf16 helpers
__device__ __forceinline__ void st_h4(__nv_bfloat16* p, const float* f) {
    uint2 u;
    *reinterpret_cast<__nv_bfloat162*>(&u.x) = __floats2bfloat162_rn(f[0], f[1]);
    *reinterpret_cast<__nv_bfloat162*>(&u.y) = __floats2bfloat162_rn(f[2], f[3]);
    *reinterpret_cast<uint2*>(p) = u;
}
__device__ __forceinline__ void st_h2(__nv_bfloat16* p, float f0, float f1) {
    unsigned u;
    *reinterpret_cast<__nv_bfloat162*>(&u) = __floats2bfloat162_rn(f0, f1);
    *reinterpret_cast<unsigned*>(p) = u;
}
__device__ __forceinline__ void acc_h4(float* acc, unsigned ux, unsigned uy, float w) {
    float2 lo = __bfloat1622float2(*reinterpret_cast<__nv_bfloat162*>(&ux));
    float2 hi = __bfloat1622float2(*reinterpret_cast<__nv_bfloat162*>(&uy));
    acc[0] += w * lo.x; acc[1] += w * lo.y; acc[2] += w * hi.x; acc[3] += w * hi.y;
}
__device__ __forceinline__ void acc_h2(float* acc, unsigned u, float w) {
    float2 lo = __bfloat1622float2(*reinterpret_cast<__nv_bfloat162*>(&u));
    acc[0] += w * lo.x; acc[1] += w * lo.y;
}

// =================== layer-0 GEMM (FIN=8 -> HC=128), parallel in-block fold ===================
__global__ void __launch_bounds__(256) k_gemm0(const float* __restrict__ xin,
                                               const float* __restrict__ W,
                                               const float* __restrict__ asrc,
                                               const float* __restrict__ adst) {
    __shared__ float Wsh[8 * 128];
    __shared__ float wfsh[32];
    __shared__ float wred[256];
    int tid = threadIdx.x, lane = tid & 31, wp = tid >> 5;
    for (int i = tid; i < 8 * 128; i += 256) Wsh[i] = W[i];
    __syncthreads();
    {
        int d = tid >> 3, e = tid & 7;
        int a = d >> 3, k = d & 7, h = a & 1;
        const float* av = ((a < 2) ? asrc : adst) + h * 64;
        const float* wr = &Wsh[k * 128 + h * 64];
        float s = 0.f;
#pragma unroll
        for (int c = 0; c < 8; c++) s += wr[e + c * 8] * av[e + c * 8];
        wred[tid] = s;
    }
    __syncthreads();
    if (tid < 32) {
        float s = 0.f;
#pragma unroll
        for (int e = 0; e < 8; e++) s += wred[tid * 8 + e];
        wfsh[tid] = s;
    }
    __syncthreads();

    const int stride = gridDim.x * 8;
    int node = blockIdx.x * 8 + wp;
    float4 pa, pb;
    if (node < NN) {
        pa = *reinterpret_cast<const float4*>(&xin[node * 8]);
        pb = *reinterpret_cast<const float4*>(&xin[node * 8 + 4]);
    }
    while (node < NN) {
        float4 xa = pa, xb = pb;
        int nnext = node + stride;
        if (nnext < NN) {
            pa = *reinterpret_cast<const float4*>(&xin[nnext * 8]);
            pb = *reinterpret_cast<const float4*>(&xin[nnext * 8 + 4]);
        }
        float xk[8] = {xa.x, xa.y, xa.z, xa.w, xb.x, xb.y, xb.z, xb.w};
        float acc[4] = {0.f, 0.f, 0.f, 0.f};
#pragma unroll
        for (int k = 0; k < 8; k++) {
            float4 w = *reinterpret_cast<const float4*>(&Wsh[k * 128 + lane * 4]);
            acc[0] += xk[k] * w.x; acc[1] += xk[k] * w.y;
            acc[2] += xk[k] * w.z; acc[3] += xk[k] * w.w;
        }
        st_h4(&g_h[(size_t)node * 128 + lane * 4], acc);

        int a = lane & 3;
        float s = 0.f;
#pragma unroll
        for (int k = 0; k < 8; k++) s += xk[k] * wfsh[a * 8 + k];
        if (lane < 2)      g_as[node * 2 + lane] = s;
        else if (lane < 4) g_ad[node * 2 + lane - 2] = s;
        node = nnext;
    }
}

// =================== CSR build ===================
__global__ void k_hist(const int* __restrict__ ei) {
    const int4* d4 = reinterpret_cast<const int4*>(ei + EE);
    for (int i = blockIdx.x * blockDim.x + threadIdx.x; i < EE / 8; i += gridDim.x * blockDim.x) {
        int4 a = d4[i * 2];
        int4 b = d4[i * 2 + 1];
        atomicAdd(&g_deg[a.x], 1);
        atomicAdd(&g_deg[a.y], 1);
        atomicAdd(&g_deg[a.z], 1);
        atomicAdd(&g_deg[a.w], 1);
        atomicAdd(&g_deg[b.x], 1);
        atomicAdd(&g_deg[b.y], 1);
        atomicAdd(&g_deg[b.z], 1);
        atomicAdd(&g_deg[b.w], 1);
    }
}
__global__ void k_scan() {
    __shared__ int sh[1024];
    const int PER = 49;
    int tid = threadIdx.x;
    int base = tid * PER;
    int s = 0;
    for (int k = 0; k < PER; k++) {
        int i = base + k;
        if (i < NN) s += g_deg[i];
    }
    sh[tid] = s;
    __syncthreads();
    for (int o = 1; o < 1024; o <<= 1) {
        int t = (tid >= o) ? sh[tid - o] : 0;
        __syncthreads();
        sh[tid] += t;
        __syncthreads();
    }
    int run = sh[tid] - s;
    for (int k = 0; k < PER; k++) {
        int i = base + k;
        if (i < NN) {
            int d = g_deg[i];
            g_off[i] = run;
            g_cur[i] = run;
            run += d;
        }
    }
    if (tid == 0) g_off[NN] = EE;
}
__global__ void k_fill(const int* __restrict__ ei) {
    const int4* s4 = reinterpret_cast<const int4*>(ei);
    const int4* d4 = reinterpret_cast<const int4*>(ei + EE);
    for (int i = blockIdx.x * blockDim.x + threadIdx.x; i < EE / 8; i += gridDim.x * blockDim.x) {
        int4 sa = s4[i * 2];
        int4 da = d4[i * 2];
        int4 sb = s4[i * 2 + 1];
        int4 db = d4[i * 2 + 1];
        int pa0 = atomicAdd(&g_cur[da.x], 1);
        int pa1 = atomicAdd(&g_cur[da.y], 1);
        int pa2 = atomicAdd(&g_cur[da.z], 1);
        int pa3 = atomicAdd(&g_cur[da.w], 1);
        int pb0 = atomicAdd(&g_cur[db.x], 1);
        int pb1 = atomicAdd(&g_cur[db.y], 1);
        int pb2 = atomicAdd(&g_cur[db.z], 1);
        int pb3 = atomicAdd(&g_cur[db.w], 1);
        g_csr[pa0] = sa.x; g_csr[pa1] = sa.y; g_csr[pa2] = sa.z; g_csr[pa3] = sa.w;
        g_csr[pb0] = sb.x; g_csr[pb1] = sb.y; g_csr[pb2] = sb.z; g_csr[pb3] = sb.w;
    }
}

// =================== tensor-core big GEMM (128 -> HC) via wmma bf16 ===================
// HC=128: tile M=64, warps 4x2 (r=w>>1, c=w&1), each warp m16 x n64 (one head).
// HC=64:  tile M=128, warps 8x1 (r=w, c=0),   each warp m16 x n64.
template <int HC>
__global__ void __launch_bounds__(256) k_gemm_wmma(const float* __restrict__ W,
                                                   const float* __restrict__ asrc,
                                                   const float* __restrict__ adst) {
    constexpr int MTILE = (HC == 128) ? 64 : 128;
    constexpr int H     = (HC == 128) ? 2 : 1;
    constexpr int XLD   = 136;                       // bf16 elems per x row (128 + pad)
    constexpr int WLD   = (HC == 128) ? 136 : 72;    // bf16 elems per W row
    constexpr int SLD   = 68;                        // fp32 elems per staging row

    extern __shared__ char smem[];
    __nv_bfloat16* xs  = reinterpret_cast<__nv_bfloat16*>(smem);                 // MTILE x XLD
    __nv_bfloat16* Wsh = xs + MTILE * XLD;                                        // 128 x WLD
    float*         stg = reinterpret_cast<float*>(Wsh + 128 * WLD);               // 8 x (16 x SLD)

    int tid = threadIdx.x, lane = tid & 31, w = tid >> 5;
    int r = (HC == 128) ? (w >> 1) : w;
    int c = (HC == 128) ? (w & 1) : 0;
    int base = blockIdx.x * MTILE;

    // load W -> bf16 smem (pairs)
    for (int i = tid; i < 128 * HC / 2; i += 256) {
        int k = (i * 2) / HC, n = (i * 2) % HC;
        float2 wv = *reinterpret_cast<const float2*>(&W[k * HC + n]);
        *reinterpret_cast<__nv_bfloat162*>(&Wsh[k * WLD + n]) = __floats2bfloat162_rn(wv.x, wv.y);
    }
    // load x tile -> bf16 smem (pairs), zero-pad OOB nodes
    for (int i = tid; i < MTILE * 64; i += 256) {
        int m = i / 64, kk = (i % 64) * 2;
        int node = base + m;
        float2 xv = (node < NN) ? *reinterpret_cast<const float2*>(&g_x[(size_t)node * 128 + kk])
                                : make_float2(0.f, 0.f);
        *reinterpret_cast<__nv_bfloat162*>(&xs[m * XLD + kk]) = __floats2bfloat162_rn(xv.x, xv.y);
    }
    __syncthreads();

    wmma::fragment<wmma::accumulator, 16, 16, 16, float> acc[4];
#pragma unroll
    for (int j = 0; j < 4; j++) wmma::fill_fragment(acc[j], 0.f);

#pragma unroll
    for (int k0 = 0; k0 < 8; k0++) {
        wmma::fragment<wmma::matrix_a, 16, 16, 16, __nv_bfloat16, wmma::row_major> af;
        wmma::load_matrix_sync(af, &xs[(r * 16) * XLD + k0 * 16], XLD);
#pragma unroll
        for (int j = 0; j < 4; j++) {
            wmma::fragment<wmma::matrix_b, 16, 16, 16, __nv_bfloat16, wmma::row_major> bf;
            wmma::load_matrix_sync(bf, &Wsh[(k0 * 16) * WLD + c * 64 + j * 16], WLD);
            wmma::mma_sync(acc[j], af, bf, acc[j]);
        }
    }

    // epilogue: fragments -> per-warp fp32 staging -> bf16 g_h + alpha dots
    float* st = stg + w * 16 * SLD;
#pragma unroll
    for (int j = 0; j < 4; j++)
        wmma::store_matrix_sync(&st[j * 16], acc[j], SLD, wmma::mem_row_major);
    __syncwarp();

    float as_lo = asrc[c * 64 + lane], as_hi = asrc[c * 64 + lane + 32];
    float ad_lo = adst[c * 64 + lane], ad_hi = adst[c * 64 + lane + 32];

#pragma unroll
    for (int i = 0; i < 16; i++) {
        int node = base + r * 16 + i;
        if (node >= NN) break;
        float2 hv = *reinterpret_cast<const float2*>(&st[i * SLD + lane * 2]);
        st_h2(&g_h[(size_t)node * HC + c * 64 + lane * 2], hv.x, hv.y);
        float e0 = st[i * SLD + lane], e1 = st[i * SLD + lane + 32];
        float vs = e0 * as_lo + e1 * as_hi;
        float vd = e0 * ad_lo + e1 * ad_hi;
#pragma unroll
        for (int o = 16; o > 0; o >>= 1) {
            vs += __shfl_down_sync(0xffffffffu, vs, o);
            vd += __shfl_down_sync(0xffffffffu, vd, o);
        }
        if (lane == 0) {
            g_as[node * H + c] = vs;
            g_ad[node * H + c] = vd;
        }
    }
}

// =================== fused softmax-aggregate (packed 64-bit gather records) ===================
template <int HC, int H, bool ACT, bool POOL>
__global__ void __launch_bounds__(256) k_agg(const float* __restrict__ bias,
                                             const int* __restrict__ batch) {
    constexpr int VEC = HC / 32;
    constexpr int ROWB = HC * 2;          // bytes per h row
    __shared__ __align__(16) unsigned long long s_rec[8][32 * H];
    int lane = threadIdx.x & 31, wp = threadIdx.x >> 5;
    int node = blockIdx.x * 8 + wp;
    if (node >= NN) return;
    int head = (H == 2) ? (lane >> 4) : 0;

    float ad0 = g_ad[node * H];
    float ad1 = (H == 2) ? g_ad[node * H + 1] : 0.f;
    int beg = g_off[node], end = g_off[node + 1];

    float acc[VEC];
#pragma unroll
    for (int v = 0; v < VEC; v++) acc[v] = 0.f;
    float d0 = 0.f, d1 = 0.f;

    const char* hb_lane = reinterpret_cast<const char*>(g_h) + lane * ((VEC == 4) ? 8 : 4);

    for (int chunk = beg; chunk < end; chunk += 32) {
        int i = chunk + lane;
        if (i < end) {
            int s = g_csr[i];
            unsigned soff = (unsigned)s * ROWB;
            if (H == 2) {
                float2 a = *reinterpret_cast<const float2*>(&g_as[s * 2]);
                float w0 = __expf(lrelu(a.x + ad0));
                float w1 = __expf(lrelu(a.y + ad1));
                d0 += w0; d1 += w1;
                *reinterpret_cast<ulonglong2*>(&s_rec[wp][lane * 2]) =
                    make_ulonglong2(pack2u(soff, w0), pack2u(soff, w1));
            } else {
                float w0 = __expf(lrelu(g_as[s] + ad0));
                d0 += w0;
                s_rec[wp][lane] = pack2u(soff, w0);
            }
        }
        __syncwarp();
        int cnt = min(32, end - chunk);
        int j = 0;
        for (; j + 8 <= cnt; j += 8) {
            unsigned soff[8];
            float    ww[8];
#pragma unroll
            for (int u = 0; u < 8; u++) {
                unsigned long long rec = (H == 2) ? s_rec[wp][(j + u) * 2 + head]
                                                  : s_rec[wp][j + u];
                unpack2u(rec, soff[u], ww[u]);
            }
            if (VEC == 4) {
                uint2 hv[8];
#pragma unroll
                for (int u = 0; u < 8; u++)
                    hv[u] = *reinterpret_cast<const uint2*>(hb_lane + soff[u]);
#pragma unroll
                for (int u = 0; u < 8; u++) acc_h4(acc, hv[u].x, hv[u].y, ww[u]);
            } else {
                unsigned hv[8];
#pragma unroll
                for (int u = 0; u < 8; u++)
                    hv[u] = *reinterpret_cast<const unsigned*>(hb_lane + soff[u]);
#pragma unroll
                for (int u = 0; u < 8; u++) acc_h2(acc, hv[u], ww[u]);
            }
        }
        for (; j + 4 <= cnt; j += 4) {
            unsigned soff[4];
            float    ww[4];
#pragma unroll
            for (int u = 0; u < 4; u++) {
                unsigned long long rec = (H == 2) ? s_rec[wp][(j + u) * 2 + head]
                                                  : s_rec[wp][j + u];
                unpack2u(rec, soff[u], ww[u]);
            }
            if (VEC == 4) {
                uint2 hv[4];
#pragma unroll
                for (int u = 0; u < 4; u++)
                    hv[u] = *reinterpret_cast<const uint2*>(hb_lane + soff[u]);
#pragma unroll
                for (int u = 0; u < 4; u++) acc_h4(acc, hv[u].x, hv[u].y, ww[u]);
            } else {
                unsigned hv[4];
#pragma unroll
                for (int u = 0; u < 4; u++)
                    hv[u] = *reinterpret_cast<const unsigned*>(hb_lane + soff[u]);
#pragma unroll
                for (int u = 0; u < 4; u++) acc_h2(acc, hv[u], ww[u]);
            }
        }
        for (; j < cnt; j++) {
            unsigned long long rec = (H == 2) ? s_rec[wp][j * 2 + head] : s_rec[wp][j];
            unsigned soff; float w;
            unpack2u(rec, soff, w);
            if (VEC == 4) {
                uint2 hv = *reinterpret_cast<const uint2*>(hb_lane + soff);
                acc_h4(acc, hv.x, hv.y, w);
            } else {
                unsigned hv = *reinterpret_cast<const unsigned*>(hb_lane + soff);
                acc_h2(acc, hv, w);
            }
        }
        __syncwarp();
    }

    // self loop
    float ws = __expf(lrelu(g_as[node * H + head] + ((H == 2 && head) ? ad1 : ad0)));
    {
        unsigned soff = (unsigned)node * ROWB;
        if (VEC == 4) {
            uint2 hv = *reinterpret_cast<const uint2*>(hb_lane + soff);
            acc_h4(acc, hv.x, hv.y, ws);
        } else {
            unsigned hv = *reinterpret_cast<const unsigned*>(hb_lane + soff);
            acc_h2(acc, hv, ws);
        }
    }

#pragma unroll
    for (int o = 16; o > 0; o >>= 1) {
        d0 += __shfl_xor_sync(0xffffffffu, d0, o);
        if (H == 2) d1 += __shfl_xor_sync(0xffffffffu, d1, o);
    }
    float dh = (H == 2 && head) ? d1 : d0;
    float inv = 1.0f / (dh + ws + 1e-16f);

    float outv[VEC];
#pragma unroll
    for (int v = 0; v < VEC; v++) {
        float t = acc[v] * inv + bias[lane * VEC + v];
        if (ACT) t = t > 0.f ? t : expm1f(t);
        outv[v] = t;
    }

    if (POOL) {
        int b = batch[node];
        float o2 = __shfl_down_sync(0xffffffffu, outv[0], 1);
        float o3 = __shfl_down_sync(0xffffffffu, outv[VEC - 1], 1);
        if ((lane & 1) == 0)
            red4(&g_pool[b * 64 + lane * 2], outv[0], outv[VEC - 1], o2, o3);
    } else {
        if (VEC == 4)
            *reinterpret_cast<float4*>(&g_x[(size_t)node * HC + lane * 4]) =
                make_float4(outv[0], outv[1], outv[2], outv[3]);
        else
            *reinterpret_cast<float2*>(&g_x[(size_t)node * HC + lane * 2]) =
                make_float2(outv[0], outv[1]);
    }
}

// =================== MLP head (counts via binary search on sorted batch) ===================
__global__ void k_mlp(const int* __restrict__ batch,
                      const float* __restrict__ obs,
                      const float* __restrict__ Ws1, const float* __restrict__ bs1,
                      const float* __restrict__ lng, const float* __restrict__ lnb,
                      const float* __restrict__ Ws2, const float* __restrict__ bs2,
                      const float* __restrict__ Wa,  const float* __restrict__ ba,
                      const float* __restrict__ Wc,  const float* __restrict__ bc,
                      float* __restrict__ out) {
    __shared__ float comb[64 + OBSD];
    __shared__ float hb[MHD];
    __shared__ float h2[MHD];
    __shared__ float rb[8];
    __shared__ float stats[2];
    __shared__ float s_cnt;

    int b = blockIdx.x;
    int tid = threadIdx.x;

    if (tid == 0) {
        int lo = 0, hi = NN;
        while (lo < hi) { int m = (lo + hi) >> 1; if (batch[m] < b) lo = m + 1; else hi = m; }
        int st = lo; lo = 0; hi = NN;
        while (lo < hi) { int m = (lo + hi) >> 1; if (batch[m] < b + 1) lo = m + 1; else hi = m; }
        s_cnt = (float)(lo - st);
    }
    __syncthreads();

    if (tid < 64)             comb[tid] = g_pool[b * 64 + tid] / fmaxf(s_cnt, 1.0f);
    else if (tid < 64 + OBSD) comb[tid] = obs[b * OBSD + (tid - 64)];
    __syncthreads();

    float s = bs1[tid];
    for (int k = 0; k < 64 + OBSD; k++) s += comb[k] * Ws1[k * MHD + tid];

    float v = s;
#pragma unroll
    for (int o = 16; o > 0; o >>= 1) v += __shfl_down_sync(0xffffffffu, v, o);
    if ((tid & 31) == 0) rb[tid >> 5] = v;
    __syncthreads();
    if (tid == 0) { float t = 0.f; for (int w = 0; w < 8; w++) t += rb[w]; stats[0] = t / MHD; }
    __syncthreads();
    float mu = stats[0];
    float dv = s - mu;
    v = dv * dv;
#pragma unroll
    for (int o = 16; o > 0; o >>= 1) v += __shfl_down_sync(0xffffffffu, v, o);
    if ((tid & 31) == 0) rb[tid >> 5] = v;
    __syncthreads();
    if (tid == 0) { float t = 0.f; for (int w = 0; w < 8; w++) t += rb[w]; stats[1] = t / MHD; }
    __syncthreads();

    float hn = dv * rsqrtf(stats[1] + 1e-5f) * lng[tid] + lnb[tid];
    hb[tid] = fmaxf(hn, 0.f);
    __syncthreads();

    float s2 = bs2[tid];
    for (int k = 0; k < MHD; k++) s2 += hb[k] * Ws2[k * MHD + tid];
    h2[tid] = fmaxf(s2, 0.f);
    __syncthreads();

    if (tid < NAD) {
        float t = ba[tid];
        for (int k = 0; k < MHD; k++) t += h2[k] * Wa[k * NAD + tid];
        out[b * NAD + tid] = t;
    }
    if (tid == NAD) {
        float t = bc[0];
        for (int k = 0; k < MHD; k++) t += h2[k] * Wc[k];
        out[BB * NAD + b] = t;
    }
}

// =================== launch ===================
static inline int gs(long long n) { return (int)((n + 255) / 256); }

extern "C" void kernel_launch(void* const* d_in, const int* in_sizes, int n_in,
                              void* d_out, int out_size) {
    const float* obs   = (const float*)d_in[0];
    const float* nf    = (const float*)d_in[1];
    const int*   ei    = (const int*)  d_in[2];
    const int*   batch = (const int*)  d_in[3];
    const float* W0 = (const float*)d_in[4];
    const float* as0 = (const float*)d_in[5];
    const float* ad0 = (const float*)d_in[6];
    const float* b0  = (const float*)d_in[7];
    const float* W1 = (const float*)d_in[8];
    const float* as1 = (const float*)d_in[9];
    const float* ad1 = (const float*)d_in[10];
    const float* b1  = (const float*)d_in[11];
    const float* W2 = (const float*)d_in[12];
    const float* as2 = (const float*)d_in[13];
    const float* ad2 = (const float*)d_in[14];
    const float* b2  = (const float*)d_in[15];
    const float* Ws1 = (const float*)d_in[16];
    const float* bs1 = (const float*)d_in[17];
    const float* lng = (const float*)d_in[18];
    const float* lnb = (const float*)d_in[19];
    const float* Ws2 = (const float*)d_in[20];
    const float* bs2 = (const float*)d_in[21];
    const float* Wa  = (const float*)d_in[22];
    const float* ba  = (const float*)d_in[23];
    const float* Wc  = (const float*)d_in[24];
    const float* bc  = (const float*)d_in[25];
    float* out = (float*)d_out;

    void *p_deg, *p_pool;
    cudaGetSymbolAddress(&p_deg,  g_deg);
    cudaGetSymbolAddress(&p_pool, g_pool);

    // dynamic smem for wmma kernels
    const int SM128 = (64 * 136 + 128 * 136) * 2 + 8 * 16 * 68 * 4;   // 87040
    const int SM64  = (128 * 136 + 128 * 72) * 2 + 8 * 16 * 68 * 4;   // 88064
    cudaFuncSetAttribute(k_gemm_wmma<128>, cudaFuncAttributeMaxDynamicSharedMemorySize, SM128);
    cudaFuncSetAttribute(k_gemm_wmma<64>,  cudaFuncAttributeMaxDynamicSharedMemorySize, SM64);

    // fork a side stream: gemm0 runs concurrently with CSR build (independent)
    cudaStream_t s2;
    cudaEvent_t evF, evJ;
    cudaStreamCreateWithFlags(&s2, cudaStreamNonBlocking);
    cudaEventCreateWithFlags(&evF, cudaEventDisableTiming);
    cudaEventCreateWithFlags(&evJ, cudaEventDisableTiming);

    cudaMemsetAsync(p_deg,  0, (NN + 1) * sizeof(int));
    cudaMemsetAsync(p_pool, 0, BB * 64 * sizeof(float));

    cudaEventRecord(evF, 0);
    cudaStreamWaitEvent(s2, evF, 0);
    k_gemm0<<<782, 256, 0, s2>>>(nf, W0, as0, ad0);     // side stream

    k_hist<<<gs(EE / 8), 256>>>(ei);                     // main stream: CSR chain
    k_scan<<<1, 1024>>>();
    k_fill<<<gs(EE / 8), 256>>>(ei);

    cudaEventRecord(evJ, s2);
    cudaStreamWaitEvent(0, evJ, 0);                      // join before agg0

    const int AGGB = (NN + 7) / 8;  // 6250

    k_agg<128, 2, true, false><<<AGGB, 256>>>(b0, nullptr);
    k_gemm_wmma<128><<<782, 256, SM128>>>(W1, as1, ad1);
    k_agg<128, 2, true, false><<<AGGB, 256>>>(b1, nullptr);
    k_gemm_wmma<64><<<391, 256, SM64>>>(W2, as2, ad2);
    k_agg<64, 1, false, true><<<AGGB, 256>>>(b2, batch);
    k_mlp<<<BB, MHD>>>(batch, obs, Ws1, bs1, lng, lnb, Ws2, bs2, Wa, ba, Wc, bc, out);
}

// round 15
// speedup vs baseline: 1.1730x; 1.0360x over previous
#include <cuda_runtime.h>
#include <cuda_bf16.h>
#include <mma.h>
#include <math.h>

#define NN 50000
#define EE 800000
#define BB 64
#define OBSD 128
#define MHD 256
#define NAD 16

using namespace nvcuda;

// ---------------- scratch ----------------
__device__ __nv_bfloat16  g_xb[NN * 128];   // layer activations (bf16; wmma rounds anyway)
__device__ __nv_bfloat16  g_h[NN * 128];
__device__ float g_as[NN * 2];
__device__ float g_ad[NN * 2];
__device__ int   g_deg[NN + 1];
__device__ int   g_off[NN + 1];
__device__ int   g_cur[NN];
__device__ int   g_csr[EE];
__device__ float g_pool[BB * 64];

__device__ __forceinline__ float lrelu(float v) { return v > 0.f ? v : 0.2f * v; }

__device__ __forceinline__ void red4(float* p, float a, float b, float c, float d) {
    asm volatile("red.global.add.v4.f32 [%0], {%1,%2,%3,%4};"
                 :: "l"(p), "f"(a), "f"(b), "f"(c), "f"(d) : "memory");
}

// ---- packed 64-bit helpers ----
__device__ __forceinline__ unsigned long long pack2u(unsigned x, float y) {
    unsigned long long r;
    asm("mov.b64 %0, {%1, %2};" : "=l"(r) : "r"(x), "r"(__float_as_uint(y)));
    return r;
}
__device__ __forceinline__ void unpack2u(unsigned long long v, unsigned& x, float& y) {
    unsigned lo, hi;
    asm("mov.b64 {%0, %1}, %2;" : "=r"(lo), "=r"(hi) : "l"(v));
    x = lo; y = __uint_as_float(hi);
}

// bf16 helpers
__device__ __forceinline__ void st_h4(__nv_bfloat16* p, const float* f) {
    uint2 u;
    *reinterpret_cast<__nv_bfloat162*>(&u.x) = __floats2bfloat162_rn(f[0], f[1]);
    *reinterpret_cast<__nv_bfloat162*>(&u.y) = __floats2bfloat162_rn(f[2], f[3]);
    *reinterpret_cast<uint2*>(p) = u;
}
__device__ __forceinline__ void st_h2(__nv_bfloat16* p, float f0, float f1) {
    unsigned u;
    *reinterpret_cast<__nv_bfloat162*>(&u) = __floats2bfloat162_rn(f0, f1);
    *reinterpret_cast<unsigned*>(p) = u;
}
__device__ __forceinline__ void acc_h4(float* acc, unsigned ux, unsigned uy, float w) {
    float2 lo = __bfloat1622float2(*reinterpret_cast<__nv_bfloat162*>(&ux));
    float2 hi = __bfloat1622float2(*reinterpret_cast<__nv_bfloat162*>(&uy));
    acc[0] += w * lo.x; acc[1] += w * lo.y; acc[2] += w * hi.x; acc[3] += w * hi.y;
}
__device__ __forceinline__ void acc_h2(float* acc, unsigned u, float w) {
    float2 lo = __bfloat1622float2(*reinterpret_cast<__nv_bfloat162*>(&u));
    acc[0] += w * lo.x; acc[1] += w * lo.y;
}

// =================== layer-0 GEMM (FIN=8 -> HC=128), parallel in-block fold ===================
__global__ void __launch_bounds__(256) k_gemm0(const float* __restrict__ xin,
                                               const float* __restrict__ W,
                                               const float* __restrict__ asrc,
                                               const float* __restrict__ adst) {
    __shared__ float Wsh[8 * 128];
    __shared__ float wfsh[32];
    __shared__ float wred[256];
    int tid = threadIdx.x, lane = tid & 31, wp = tid >> 5;
    for (int i = tid; i < 8 * 128; i += 256) Wsh[i] = W[i];
    __syncthreads();
    {
        int d = tid >> 3, e = tid & 7;
        int a = d >> 3, k = d & 7, h = a & 1;
        const float* av = ((a < 2) ? asrc : adst) + h * 64;
        const float* wr = &Wsh[k * 128 + h * 64];
        float s = 0.f;
#pragma unroll
        for (int c = 0; c < 8; c++) s += wr[e + c * 8] * av[e + c * 8];
        wred[tid] = s;
    }
    __syncthreads();
    if (tid < 32) {
        float s = 0.f;
#pragma unroll
        for (int e = 0; e < 8; e++) s += wred[tid * 8 + e];
        wfsh[tid] = s;
    }
    __syncthreads();

    const int stride = gridDim.x * 8;
    int node = blockIdx.x * 8 + wp;
    float4 pa, pb;
    if (node < NN) {
        pa = *reinterpret_cast<const float4*>(&xin[node * 8]);
        pb = *reinterpret_cast<const float4*>(&xin[node * 8 + 4]);
    }
    while (node < NN) {
        float4 xa = pa, xb = pb;
        int nnext = node + stride;
        if (nnext < NN) {
            pa = *reinterpret_cast<const float4*>(&xin[nnext * 8]);
            pb = *reinterpret_cast<const float4*>(&xin[nnext * 8 + 4]);
        }
        float xk[8] = {xa.x, xa.y, xa.z, xa.w, xb.x, xb.y, xb.z, xb.w};
        float acc[4] = {0.f, 0.f, 0.f, 0.f};
#pragma unroll
        for (int k = 0; k < 8; k++) {
            float4 w = *reinterpret_cast<const float4*>(&Wsh[k * 128 + lane * 4]);
            acc[0] += xk[k] * w.x; acc[1] += xk[k] * w.y;
            acc[2] += xk[k] * w.z; acc[3] += xk[k] * w.w;
        }
        st_h4(&g_h[(size_t)node * 128 + lane * 4], acc);

        int a = lane & 3;
        float s = 0.f;
#pragma unroll
        for (int k = 0; k < 8; k++) s += xk[k] * wfsh[a * 8 + k];
        if (lane < 2)      g_as[node * 2 + lane] = s;
        else if (lane < 4) g_ad[node * 2 + lane - 2] = s;
        node = nnext;
    }
}

// =================== CSR build ===================
__global__ void k_hist(const int* __restrict__ ei) {
    const int4* d4 = reinterpret_cast<const int4*>(ei + EE);
    for (int i = blockIdx.x * blockDim.x + threadIdx.x; i < EE / 8; i += gridDim.x * blockDim.x) {
        int4 a = d4[i * 2];
        int4 b = d4[i * 2 + 1];
        atomicAdd(&g_deg[a.x], 1);
        atomicAdd(&g_deg[a.y], 1);
        atomicAdd(&g_deg[a.z], 1);
        atomicAdd(&g_deg[a.w], 1);
        atomicAdd(&g_deg[b.x], 1);
        atomicAdd(&g_deg[b.y], 1);
        atomicAdd(&g_deg[b.z], 1);
        atomicAdd(&g_deg[b.w], 1);
    }
}
__global__ void k_scan() {
    __shared__ int sh[1024];
    const int PER = 49;
    int tid = threadIdx.x;
    int base = tid * PER;
    int s = 0;
    for (int k = 0; k < PER; k++) {
        int i = base + k;
        if (i < NN) s += g_deg[i];
    }
    sh[tid] = s;
    __syncthreads();
    for (int o = 1; o < 1024; o <<= 1) {
        int t = (tid >= o) ? sh[tid - o] : 0;
        __syncthreads();
        sh[tid] += t;
        __syncthreads();
    }
    int run = sh[tid] - s;
    for (int k = 0; k < PER; k++) {
        int i = base + k;
        if (i < NN) {
            int d = g_deg[i];
            g_off[i] = run;
            g_cur[i] = run;
            run += d;
        }
    }
    if (tid == 0) g_off[NN] = EE;
}
__global__ void k_fill(const int* __restrict__ ei) {
    const int4* s4 = reinterpret_cast<const int4*>(ei);
    const int4* d4 = reinterpret_cast<const int4*>(ei + EE);
    for (int i = blockIdx.x * blockDim.x + threadIdx.x; i < EE / 8; i += gridDim.x * blockDim.x) {
        int4 sa = s4[i * 2];
        int4 da = d4[i * 2];
        int4 sb = s4[i * 2 + 1];
        int4 db = d4[i * 2 + 1];
        int pa0 = atomicAdd(&g_cur[da.x], 1);
        int pa1 = atomicAdd(&g_cur[da.y], 1);
        int pa2 = atomicAdd(&g_cur[da.z], 1);
        int pa3 = atomicAdd(&g_cur[da.w], 1);
        int pb0 = atomicAdd(&g_cur[db.x], 1);
        int pb1 = atomicAdd(&g_cur[db.y], 1);
        int pb2 = atomicAdd(&g_cur[db.z], 1);
        int pb3 = atomicAdd(&g_cur[db.w], 1);
        g_csr[pa0] = sa.x; g_csr[pa1] = sa.y; g_csr[pa2] = sa.z; g_csr[pa3] = sa.w;
        g_csr[pb0] = sb.x; g_csr[pb1] = sb.y; g_csr[pb2] = sb.z; g_csr[pb3] = sb.w;
    }
}

// =================== tensor-core big GEMM (128 -> HC) via wmma bf16 ===================
template <int HC>
__global__ void __launch_bounds__(256) k_gemm_wmma(const float* __restrict__ W,
                                                   const float* __restrict__ asrc,
                                                   const float* __restrict__ adst) {
    constexpr int MTILE = (HC == 128) ? 64 : 128;
    constexpr int H     = (HC == 128) ? 2 : 1;
    constexpr int XLD   = 136;                       // bf16 elems per x row (128 + pad)
    constexpr int WLD   = (HC == 128) ? 136 : 72;    // bf16 elems per W row
    constexpr int SLD   = 68;                        // fp32 elems per staging row

    extern __shared__ char smem[];
    __nv_bfloat16* xs  = reinterpret_cast<__nv_bfloat16*>(smem);                 // MTILE x XLD
    __nv_bfloat16* Wsh = xs + MTILE * XLD;                                        // 128 x WLD
    float*         stg = reinterpret_cast<float*>(Wsh + 128 * WLD);               // 8 x (16 x SLD)

    int tid = threadIdx.x, lane = tid & 31, w = tid >> 5;
    int r = (HC == 128) ? (w >> 1) : w;
    int c = (HC == 128) ? (w & 1) : 0;
    int base = blockIdx.x * MTILE;

    // load W -> bf16 smem (pairs)
    for (int i = tid; i < 128 * HC / 2; i += 256) {
        int k = (i * 2) / HC, n = (i * 2) % HC;
        float2 wv = *reinterpret_cast<const float2*>(&W[k * HC + n]);
        *reinterpret_cast<__nv_bfloat162*>(&Wsh[k * WLD + n]) = __floats2bfloat162_rn(wv.x, wv.y);
    }
    // load x tile (already bf16) -> smem as raw uint4 (8 bf16 per chunk)
    for (int i = tid; i < MTILE * 16; i += 256) {
        int m = i / 16, q = i % 16;
        int node = base + m;
        uint4 v = (node < NN)
            ? *reinterpret_cast<const uint4*>(&g_xb[(size_t)node * 128 + q * 8])
            : make_uint4(0u, 0u, 0u, 0u);
        *reinterpret_cast<uint4*>(&xs[m * XLD + q * 8]) = v;
    }
    __syncthreads();

    wmma::fragment<wmma::accumulator, 16, 16, 16, float> acc[4];
#pragma unroll
    for (int j = 0; j < 4; j++) wmma::fill_fragment(acc[j], 0.f);

#pragma unroll
    for (int k0 = 0; k0 < 8; k0++) {
        wmma::fragment<wmma::matrix_a, 16, 16, 16, __nv_bfloat16, wmma::row_major> af;
        wmma::load_matrix_sync(af, &xs[(r * 16) * XLD + k0 * 16], XLD);
#pragma unroll
        for (int j = 0; j < 4; j++) {
            wmma::fragment<wmma::matrix_b, 16, 16, 16, __nv_bfloat16, wmma::row_major> bf;
            wmma::load_matrix_sync(bf, &Wsh[(k0 * 16) * WLD + c * 64 + j * 16], WLD);
            wmma::mma_sync(acc[j], af, bf, acc[j]);
        }
    }

    // epilogue: fragments -> per-warp fp32 staging -> bf16 g_h + alpha dots
    float* st = stg + w * 16 * SLD;
#pragma unroll
    for (int j = 0; j < 4; j++)
        wmma::store_matrix_sync(&st[j * 16], acc[j], SLD, wmma::mem_row_major);
    __syncwarp();

    float as_lo = asrc[c * 64 + lane], as_hi = asrc[c * 64 + lane + 32];
    float ad_lo = adst[c * 64 + lane], ad_hi = adst[c * 64 + lane + 32];

#pragma unroll
    for (int i = 0; i < 16; i++) {
        int node = base + r * 16 + i;
        if (node >= NN) break;
        float2 hv = *reinterpret_cast<const float2*>(&st[i * SLD + lane * 2]);
        st_h2(&g_h[(size_t)node * HC + c * 64 + lane * 2], hv.x, hv.y);
        float e0 = st[i * SLD + lane], e1 = st[i * SLD + lane + 32];
        float vs = e0 * as_lo + e1 * as_hi;
        float vd = e0 * ad_lo + e1 * ad_hi;
#pragma unroll
        for (int o = 16; o > 0; o >>= 1) {
            vs += __shfl_down_sync(0xffffffffu, vs, o);
            vd += __shfl_down_sync(0xffffffffu, vd, o);
        }
        if (lane == 0) {
            g_as[node * H + c] = vs;
            g_ad[node * H + c] = vd;
        }
    }
}

// =================== fused softmax-aggregate (grid-stride warps: ~4 nodes/warp) ===================
template <int HC, int H, bool ACT, bool POOL>
__global__ void __launch_bounds__(256) k_agg(const float* __restrict__ bias,
                                             const int* __restrict__ batch) {
    constexpr int VEC = HC / 32;
    constexpr int ROWB = HC * 2;          // bytes per h row
    __shared__ __align__(16) unsigned long long s_rec[8][32 * H];
    int lane = threadIdx.x & 31, wp = threadIdx.x >> 5;
    int head = (H == 2) ? (lane >> 4) : 0;
    const int stride = gridDim.x * 8;
    const char* hb_lane = reinterpret_cast<const char*>(g_h) + lane * ((VEC == 4) ? 8 : 4);

    for (int node = blockIdx.x * 8 + wp; node < NN; node += stride) {
        float ad0 = g_ad[node * H];
        float ad1 = (H == 2) ? g_ad[node * H + 1] : 0.f;
        int beg = g_off[node], end = g_off[node + 1];

        float acc[VEC];
#pragma unroll
        for (int v = 0; v < VEC; v++) acc[v] = 0.f;
        float d0 = 0.f, d1 = 0.f;

        for (int chunk = beg; chunk < end; chunk += 32) {
            int i = chunk + lane;
            if (i < end) {
                int s = g_csr[i];
                unsigned soff = (unsigned)s * ROWB;
                if (H == 2) {
                    float2 a = *reinterpret_cast<const float2*>(&g_as[s * 2]);
                    float w0 = __expf(lrelu(a.x + ad0));
                    float w1 = __expf(lrelu(a.y + ad1));
                    d0 += w0; d1 += w1;
                    *reinterpret_cast<ulonglong2*>(&s_rec[wp][lane * 2]) =
                        make_ulonglong2(pack2u(soff, w0), pack2u(soff, w1));
                } else {
                    float w0 = __expf(lrelu(g_as[s] + ad0));
                    d0 += w0;
                    s_rec[wp][lane] = pack2u(soff, w0);
                }
            }
            __syncwarp();
            int cnt = min(32, end - chunk);
            int j = 0;
            for (; j + 8 <= cnt; j += 8) {
                unsigned soff[8];
                float    ww[8];
#pragma unroll
                for (int u = 0; u < 8; u++) {
                    unsigned long long rec = (H == 2) ? s_rec[wp][(j + u) * 2 + head]
                                                      : s_rec[wp][j + u];
                    unpack2u(rec, soff[u], ww[u]);
                }
                if (VEC == 4) {
                    uint2 hv[8];
#pragma unroll
                    for (int u = 0; u < 8; u++)
                        hv[u] = *reinterpret_cast<const uint2*>(hb_lane + soff[u]);
#pragma unroll
                    for (int u = 0; u < 8; u++) acc_h4(acc, hv[u].x, hv[u].y, ww[u]);
                } else {
                    unsigned hv[8];
#pragma unroll
                    for (int u = 0; u < 8; u++)
                        hv[u] = *reinterpret_cast<const unsigned*>(hb_lane + soff[u]);
#pragma unroll
                    for (int u = 0; u < 8; u++) acc_h2(acc, hv[u], ww[u]);
                }
            }
            for (; j + 4 <= cnt; j += 4) {
                unsigned soff[4];
                float    ww[4];
#pragma unroll
                for (int u = 0; u < 4; u++) {
                    unsigned long long rec = (H == 2) ? s_rec[wp][(j + u) * 2 + head]
                                                      : s_rec[wp][j + u];
                    unpack2u(rec, soff[u], ww[u]);
                }
                if (VEC == 4) {
                    uint2 hv[4];
#pragma unroll
                    for (int u = 0; u < 4; u++)
                        hv[u] = *reinterpret_cast<const uint2*>(hb_lane + soff[u]);
#pragma unroll
                    for (int u = 0; u < 4; u++) acc_h4(acc, hv[u].x, hv[u].y, ww[u]);
                } else {
                    unsigned hv[4];
#pragma unroll
                    for (int u = 0; u < 4; u++)
                        hv[u] = *reinterpret_cast<const unsigned*>(hb_lane + soff[u]);
#pragma unroll
                    for (int u = 0; u < 4; u++) acc_h2(acc, hv[u], ww[u]);
                }
            }
            for (; j < cnt; j++) {
                unsigned long long rec = (H == 2) ? s_rec[wp][j * 2 + head] : s_rec[wp][j];
                unsigned soff; float w;
                unpack2u(rec, soff, w);
                if (VEC == 4) {
                    uint2 hv = *reinterpret_cast<const uint2*>(hb_lane + soff);
                    acc_h4(acc, hv.x, hv.y, w);
                } else {
                    unsigned hv = *reinterpret_cast<const unsigned*>(hb_lane + soff);
                    acc_h2(acc, hv, w);
                }
            }
            __syncwarp();
        }

        // self loop
        float ws = __expf(lrelu(g_as[node * H + head] + ((H == 2 && head) ? ad1 : ad0)));
        {
            unsigned soff = (unsigned)node * ROWB;
            if (VEC == 4) {
                uint2 hv = *reinterpret_cast<const uint2*>(hb_lane + soff);
                acc_h4(acc, hv.x, hv.y, ws);
            } else {
                unsigned hv = *reinterpret_cast<const unsigned*>(hb_lane + soff);
                acc_h2(acc, hv, ws);
            }
        }

#pragma unroll
        for (int o = 16; o > 0; o >>= 1) {
            d0 += __shfl_xor_sync(0xffffffffu, d0, o);
            if (H == 2) d1 += __shfl_xor_sync(0xffffffffu, d1, o);
        }
        float dh = (H == 2 && head) ? d1 : d0;
        float inv = 1.0f / (dh + ws + 1e-16f);

        float outv[VEC];
#pragma unroll
        for (int v = 0; v < VEC; v++) {
            float t = acc[v] * inv + bias[lane * VEC + v];
            if (ACT) t = t > 0.f ? t : expm1f(t);
            outv[v] = t;
        }

        if (POOL) {
            int b = batch[node];
            float o2 = __shfl_down_sync(0xffffffffu, outv[0], 1);
            float o3 = __shfl_down_sync(0xffffffffu, outv[VEC - 1], 1);
            if ((lane & 1) == 0)
                red4(&g_pool[b * 64 + lane * 2], outv[0], outv[VEC - 1], o2, o3);
        } else {
            if (VEC == 4) st_h4(&g_xb[(size_t)node * HC + lane * 4], outv);
            else          st_h2(&g_xb[(size_t)node * HC + lane * 2], outv[0], outv[1]);
        }
    }
}

// =================== MLP head (counts via binary search on sorted batch) ===================
__global__ void k_mlp(const int* __restrict__ batch,
                      const float* __restrict__ obs,
                      const float* __restrict__ Ws1, const float* __restrict__ bs1,
                      const float* __restrict__ lng, const float* __restrict__ lnb,
                      const float* __restrict__ Ws2, const float* __restrict__ bs2,
                      const float* __restrict__ Wa,  const float* __restrict__ ba,
                      const float* __restrict__ Wc,  const float* __restrict__ bc,
                      float* __restrict__ out) {
    __shared__ float comb[64 + OBSD];
    __shared__ float hb[MHD];
    __shared__ float h2[MHD];
    __shared__ float rb[8];
    __shared__ float stats[2];
    __shared__ float s_cnt;

    int b = blockIdx.x;
    int tid = threadIdx.x;

    if (tid == 0) {
        int lo = 0, hi = NN;
        while (lo < hi) { int m = (lo + hi) >> 1; if (batch[m] < b) lo = m + 1; else hi = m; }
        int st = lo; lo = 0; hi = NN;
        while (lo < hi) { int m = (lo + hi) >> 1; if (batch[m] < b + 1) lo = m + 1; else hi = m; }
        s_cnt = (float)(lo - st);
    }
    __syncthreads();

    if (tid < 64)             comb[tid] = g_pool[b * 64 + tid] / fmaxf(s_cnt, 1.0f);
    else if (tid < 64 + OBSD) comb[tid] = obs[b * OBSD + (tid - 64)];
    __syncthreads();

    float s = bs1[tid];
    for (int k = 0; k < 64 + OBSD; k++) s += comb[k] * Ws1[k * MHD + tid];

    float v = s;
#pragma unroll
    for (int o = 16; o > 0; o >>= 1) v += __shfl_down_sync(0xffffffffu, v, o);
    if ((tid & 31) == 0) rb[tid >> 5] = v;
    __syncthreads();
    if (tid == 0) { float t = 0.f; for (int w = 0; w < 8; w++) t += rb[w]; stats[0] = t / MHD; }
    __syncthreads();
    float mu = stats[0];
    float dv = s - mu;
    v = dv * dv;
#pragma unroll
    for (int o = 16; o > 0; o >>= 1) v += __shfl_down_sync(0xffffffffu, v, o);
    if ((tid & 31) == 0) rb[tid >> 5] = v;
    __syncthreads();
    if (tid == 0) { float t = 0.f; for (int w = 0; w < 8; w++) t += rb[w]; stats[1] = t / MHD; }
    __syncthreads();

    float hn = dv * rsqrtf(stats[1] + 1e-5f) * lng[tid] + lnb[tid];
    hb[tid] = fmaxf(hn, 0.f);
    __syncthreads();

    float s2 = bs2[tid];
    for (int k = 0; k < MHD; k++) s2 += hb[k] * Ws2[k * MHD + tid];
    h2[tid] = fmaxf(s2, 0.f);
    __syncthreads();

    if (tid < NAD) {
        float t = ba[tid];
        for (int k = 0; k < MHD; k++) t += h2[k] * Wa[k * NAD + tid];
        out[b * NAD + tid] = t;
    }
    if (tid == NAD) {
        float t = bc[0];
        for (int k = 0; k < MHD; k++) t += h2[k] * Wc[k];
        out[BB * NAD + b] = t;
    }
}

// =================== launch ===================
static inline int gs(long long n) { return (int)((n + 255) / 256); }

extern "C" void kernel_launch(void* const* d_in, const int* in_sizes, int n_in,
                              void* d_out, int out_size) {
    const float* obs   = (const float*)d_in[0];
    const float* nf    = (const float*)d_in[1];
    const int*   ei    = (const int*)  d_in[2];
    const int*   batch = (const int*)  d_in[3];
    const float* W0 = (const float*)d_in[4];
    const float* as0 = (const float*)d_in[5];
    const float* ad0 = (const float*)d_in[6];
    const float* b0  = (const float*)d_in[7];
    const float* W1 = (const float*)d_in[8];
    const float* as1 = (const float*)d_in[9];
    const float* ad1 = (const float*)d_in[10];
    const float* b1  = (const float*)d_in[11];
    const float* W2 = (const float*)d_in[12];
    const float* as2 = (const float*)d_in[13];
    const float* ad2 = (const float*)d_in[14];
    const float* b2  = (const float*)d_in[15];
    const float* Ws1 = (const float*)d_in[16];
    const float* bs1 = (const float*)d_in[17];
    const float* lng = (const float*)d_in[18];
    const float* lnb = (const float*)d_in[19];
    const float* Ws2 = (const float*)d_in[20];
    const float* bs2 = (const float*)d_in[21];
    const float* Wa  = (const float*)d_in[22];
    const float* ba  = (const float*)d_in[23];
    const float* Wc  = (const float*)d_in[24];
    const float* bc  = (const float*)d_in[25];
    float* out = (float*)d_out;

    void *p_deg, *p_pool;
    cudaGetSymbolAddress(&p_deg,  g_deg);
    cudaGetSymbolAddress(&p_pool, g_pool);

    // dynamic smem for wmma kernels
    const int SM128 = (64 * 136 + 128 * 136) * 2 + 8 * 16 * 68 * 4;   // 87040
    const int SM64  = (128 * 136 + 128 * 72) * 2 + 8 * 16 * 68 * 4;   // 88064
    cudaFuncSetAttribute(k_gemm_wmma<128>, cudaFuncAttributeMaxDynamicSharedMemorySize, SM128);
    cudaFuncSetAttribute(k_gemm_wmma<64>,  cudaFuncAttributeMaxDynamicSharedMemorySize, SM64);

    // fork a side stream: gemm0 runs concurrently with CSR build (independent)
    cudaStream_t s2;
    cudaEvent_t evF, evJ;
    cudaStreamCreateWithFlags(&s2, cudaStreamNonBlocking);
    cudaEventCreateWithFlags(&evF, cudaEventDisableTiming);
    cudaEventCreateWithFlags(&evJ, cudaEventDisableTiming);

    cudaMemsetAsync(p_deg,  0, (NN + 1) * sizeof(int));
    cudaMemsetAsync(p_pool, 0, BB * 64 * sizeof(float));

    cudaEventRecord(evF, 0);
    cudaStreamWaitEvent(s2, evF, 0);
    k_gemm0<<<782, 256, 0, s2>>>(nf, W0, as0, ad0);     // side stream

    k_hist<<<gs(EE / 8), 256>>>(ei);                     // main stream: CSR chain
    k_scan<<<1, 1024>>>();
    k_fill<<<gs(EE / 8), 256>>>(ei);

    cudaEventRecord(evJ, s2);
    cudaStreamWaitEvent(0, evJ, 0);                      // join before agg0

    const int AGGB = 1563;   // grid-stride: ~4 nodes per warp (degree-imbalance smoothing)

    k_agg<128, 2, true, false><<<AGGB, 256>>>(b0, nullptr);
    k_gemm_wmma<128><<<782, 256, SM128>>>(W1, as1, ad1);
    k_agg<128, 2, true, false><<<AGGB, 256>>>(b1, nullptr);
    k_gemm_wmma<64><<<391, 256, SM64>>>(W2, as2, ad2);
    k_agg<64, 1, false, true><<<AGGB, 256>>>(b2, batch);
    k_mlp<<<BB, MHD>>>(batch, obs, Ws1, bs1, lng, lnb, Ws2, bs2, Wa, ba, Wc, bc, out);
}

// round 16
// speedup vs baseline: 1.1919x; 1.0161x over previous
#include <cuda_runtime.h>
#include <cuda_bf16.h>
#include <mma.h>
#include <math.h>

#define NN 50000
#define EE 800000
#define BB 64
#define OBSD 128
#define MHD 256
#define NAD 16

using namespace nvcuda;

// ---------------- scratch ----------------
__device__ __nv_bfloat16  g_xb[NN * 128];   // layer activations (bf16)
__device__ __nv_bfloat16  g_h[NN * 128];    // h = x @ W (layers 1/2)
__device__ __nv_bfloat16  g_x8[NN * 8];     // layer-0 input, bf16
__device__ float g_as[NN * 2];
__device__ float g_ad[NN * 2];
__device__ int   g_deg[NN + 1];
__device__ int   g_off[NN + 1];
__device__ int   g_cur[NN];
__device__ int   g_csr[EE];
__device__ float g_pool[BB * 64];

__device__ __forceinline__ float lrelu(float v) { return v > 0.f ? v : 0.2f * v; }

__device__ __forceinline__ void red4(float* p, float a, float b, float c, float d) {
    asm volatile("red.global.add.v4.f32 [%0], {%1,%2,%3,%4};"
                 :: "l"(p), "f"(a), "f"(b), "f"(c), "f"(d) : "memory");
}

// ---- packed 64-bit helpers ----
__device__ __forceinline__ unsigned long long pack2u(unsigned x, float y) {
    unsigned long long r;
    asm("mov.b64 %0, {%1, %2};" : "=l"(r) : "r"(x), "r"(__float_as_uint(y)));
    return r;
}
__device__ __forceinline__ void unpack2u(unsigned long long v, unsigned& x, float& y) {
    unsigned lo, hi;
    asm("mov.b64 {%0, %1}, %2;" : "=r"(lo), "=r"(hi) : "l"(v));
    x = lo; y = __uint_as_float(hi);
}

// bf16 helpers
__device__ __forceinline__ void st_h4(__nv_bfloat16* p, const float* f) {
    uint2 u;
    *reinterpret_cast<__nv_bfloat162*>(&u.x) = __floats2bfloat162_rn(f[0], f[1]);
    *reinterpret_cast<__nv_bfloat162*>(&u.y) = __floats2bfloat162_rn(f[2], f[3]);
    *reinterpret_cast<uint2*>(p) = u;
}
__device__ __forceinline__ void st_h2(__nv_bfloat16* p, float f0, float f1) {
    unsigned u;
    *reinterpret_cast<__nv_bfloat162*>(&u) = __floats2bfloat162_rn(f0, f1);
    *reinterpret_cast<unsigned*>(p) = u;
}
__device__ __forceinline__ void acc_h4(float* acc, unsigned ux, unsigned uy, float w) {
    float2 lo = __bfloat1622float2(*reinterpret_cast<__nv_bfloat162*>(&ux));
    float2 hi = __bfloat1622float2(*reinterpret_cast<__nv_bfloat162*>(&uy));
    acc[0] += w * lo.x; acc[1] += w * lo.y; acc[2] += w * hi.x; acc[3] += w * hi.y;
}
__device__ __forceinline__ void acc_h2(float* acc, unsigned u, float w) {
    float2 lo = __bfloat1622float2(*reinterpret_cast<__nv_bfloat162*>(&u));
    acc[0] += w * lo.x; acc[1] += w * lo.y;
}
__device__ __forceinline__ void unpack8(uint4 v, float* f) {
    float2 a = __bfloat1622float2(*reinterpret_cast<__nv_bfloat162*>(&v.x));
    float2 b = __bfloat1622float2(*reinterpret_cast<__nv_bfloat162*>(&v.y));
    float2 c = __bfloat1622float2(*reinterpret_cast<__nv_bfloat162*>(&v.z));
    float2 d = __bfloat1622float2(*reinterpret_cast<__nv_bfloat162*>(&v.w));
    f[0] = a.x; f[1] = a.y; f[2] = b.x; f[3] = b.y;
    f[4] = c.x; f[5] = c.y; f[6] = d.x; f[7] = d.y;
}

// =================== prep0: bf16 x8 copy + alpha0 via folded dots ===================
__global__ void __launch_bounds__(256) k_prep0(const float* __restrict__ xin,
                                               const float* __restrict__ W0,
                                               const float* __restrict__ asrc,
                                               const float* __restrict__ adst) {
    __shared__ float Wsh[8 * 128];
    __shared__ float wfsh[32];
    __shared__ float wred[256];
    int tid = threadIdx.x;
    for (int i = tid; i < 8 * 128; i += 256) Wsh[i] = W0[i];
    __syncthreads();
    {
        int d = tid >> 3, e = tid & 7;
        int a = d >> 3, k = d & 7, h = a & 1;
        const float* av = ((a < 2) ? asrc : adst) + h * 64;
        const float* wr = &Wsh[k * 128 + h * 64];
        float s = 0.f;
#pragma unroll
        for (int c = 0; c < 8; c++) s += wr[e + c * 8] * av[e + c * 8];
        wred[tid] = s;
    }
    __syncthreads();
    if (tid < 32) {
        float s = 0.f;
#pragma unroll
        for (int e = 0; e < 8; e++) s += wred[tid * 8 + e];
        wfsh[tid] = s;
    }
    __syncthreads();

    for (int node = blockIdx.x * 256 + tid; node < NN; node += gridDim.x * 256) {
        float4 xa = *reinterpret_cast<const float4*>(&xin[node * 8]);
        float4 xb = *reinterpret_cast<const float4*>(&xin[node * 8 + 4]);
        float xk[8] = {xa.x, xa.y, xa.z, xa.w, xb.x, xb.y, xb.z, xb.w};
        float s0 = 0.f, s1 = 0.f, d0 = 0.f, d1 = 0.f;
#pragma unroll
        for (int k = 0; k < 8; k++) {
            s0 += xk[k] * wfsh[0 * 8 + k];
            s1 += xk[k] * wfsh[1 * 8 + k];
            d0 += xk[k] * wfsh[2 * 8 + k];
            d1 += xk[k] * wfsh[3 * 8 + k];
        }
        *reinterpret_cast<float2*>(&g_as[node * 2]) = make_float2(s0, s1);
        *reinterpret_cast<float2*>(&g_ad[node * 2]) = make_float2(d0, d1);
        uint4 u;
        *reinterpret_cast<__nv_bfloat162*>(&u.x) = __floats2bfloat162_rn(xk[0], xk[1]);
        *reinterpret_cast<__nv_bfloat162*>(&u.y) = __floats2bfloat162_rn(xk[2], xk[3]);
        *reinterpret_cast<__nv_bfloat162*>(&u.z) = __floats2bfloat162_rn(xk[4], xk[5]);
        *reinterpret_cast<__nv_bfloat162*>(&u.w) = __floats2bfloat162_rn(xk[6], xk[7]);
        *reinterpret_cast<uint4*>(&g_x8[node * 8]) = u;
    }
}

// =================== CSR build ===================
__global__ void k_hist(const int* __restrict__ ei) {
    const int4* d4 = reinterpret_cast<const int4*>(ei + EE);
    for (int i = blockIdx.x * blockDim.x + threadIdx.x; i < EE / 8; i += gridDim.x * blockDim.x) {
        int4 a = d4[i * 2];
        int4 b = d4[i * 2 + 1];
        atomicAdd(&g_deg[a.x], 1);
        atomicAdd(&g_deg[a.y], 1);
        atomicAdd(&g_deg[a.z], 1);
        atomicAdd(&g_deg[a.w], 1);
        atomicAdd(&g_deg[b.x], 1);
        atomicAdd(&g_deg[b.y], 1);
        atomicAdd(&g_deg[b.z], 1);
        atomicAdd(&g_deg[b.w], 1);
    }
}
__global__ void k_scan() {
    __shared__ int sh[1024];
    const int PER = 49;
    int tid = threadIdx.x;
    int base = tid * PER;
    int s = 0;
    for (int k = 0; k < PER; k++) {
        int i = base + k;
        if (i < NN) s += g_deg[i];
    }
    sh[tid] = s;
    __syncthreads();
    for (int o = 1; o < 1024; o <<= 1) {
        int t = (tid >= o) ? sh[tid - o] : 0;
        __syncthreads();
        sh[tid] += t;
        __syncthreads();
    }
    int run = sh[tid] - s;
    for (int k = 0; k < PER; k++) {
        int i = base + k;
        if (i < NN) {
            int d = g_deg[i];
            g_off[i] = run;
            g_cur[i] = run;
            run += d;
        }
    }
    if (tid == 0) g_off[NN] = EE;
}
__global__ void k_fill(const int* __restrict__ ei) {
    const int4* s4 = reinterpret_cast<const int4*>(ei);
    const int4* d4 = reinterpret_cast<const int4*>(ei + EE);
    for (int i = blockIdx.x * blockDim.x + threadIdx.x; i < EE / 8; i += gridDim.x * blockDim.x) {
        int4 sa = s4[i * 2];
        int4 da = d4[i * 2];
        int4 sb = s4[i * 2 + 1];
        int4 db = d4[i * 2 + 1];
        int pa0 = atomicAdd(&g_cur[da.x], 1);
        int pa1 = atomicAdd(&g_cur[da.y], 1);
        int pa2 = atomicAdd(&g_cur[da.z], 1);
        int pa3 = atomicAdd(&g_cur[da.w], 1);
        int pb0 = atomicAdd(&g_cur[db.x], 1);
        int pb1 = atomicAdd(&g_cur[db.y], 1);
        int pb2 = atomicAdd(&g_cur[db.z], 1);
        int pb3 = atomicAdd(&g_cur[db.w], 1);
        g_csr[pa0] = sa.x; g_csr[pa1] = sa.y; g_csr[pa2] = sa.z; g_csr[pa3] = sa.w;
        g_csr[pb0] = sb.x; g_csr[pb1] = sb.y; g_csr[pb2] = sb.z; g_csr[pb3] = sb.w;
    }
}

// =================== layer-0 aggregate on 8-dim x (lane-per-edge) + W0 transform ===================
__global__ void __launch_bounds__(256) k_agg0x(const float* __restrict__ W0,
                                               const float* __restrict__ bias) {
    __shared__ float Wsh[8 * 128];
    int tid = threadIdx.x, lane = tid & 31, wp = tid >> 5;
    for (int i = tid; i < 8 * 128; i += 256) Wsh[i] = W0[i];
    __syncthreads();

    for (int node = blockIdx.x * 8 + wp; node < NN; node += gridDim.x * 8) {
        float2 adp = *reinterpret_cast<const float2*>(&g_ad[node * 2]);
        float ad00 = adp.x, ad01 = adp.y;
        int beg = g_off[node], end = g_off[node + 1];

        float ax0[8], ax1[8];
#pragma unroll
        for (int k = 0; k < 8; k++) { ax0[k] = 0.f; ax1[k] = 0.f; }
        float d0 = 0.f, d1 = 0.f;

        for (int i = beg + lane; i < end; i += 32) {
            int s = g_csr[i];
            float2 a = *reinterpret_cast<const float2*>(&g_as[s * 2]);
            float w0 = __expf(lrelu(a.x + ad00));
            float w1 = __expf(lrelu(a.y + ad01));
            d0 += w0; d1 += w1;
            uint4 xv = *reinterpret_cast<const uint4*>(&g_x8[s * 8]);
            float xk[8];
            unpack8(xv, xk);
#pragma unroll
            for (int k = 0; k < 8; k++) { ax0[k] += w0 * xk[k]; ax1[k] += w1 * xk[k]; }
        }
        if (lane == 0) {   // self loop
            float2 a = *reinterpret_cast<const float2*>(&g_as[node * 2]);
            float w0 = __expf(lrelu(a.x + ad00));
            float w1 = __expf(lrelu(a.y + ad01));
            d0 += w0; d1 += w1;
            uint4 xv = *reinterpret_cast<const uint4*>(&g_x8[node * 8]);
            float xk[8];
            unpack8(xv, xk);
#pragma unroll
            for (int k = 0; k < 8; k++) { ax0[k] += w0 * xk[k]; ax1[k] += w1 * xk[k]; }
        }

        // butterfly-reduce 18 values across the warp
#pragma unroll
        for (int o = 16; o > 0; o >>= 1) {
#pragma unroll
            for (int k = 0; k < 8; k++) {
                ax0[k] += __shfl_xor_sync(0xffffffffu, ax0[k], o);
                ax1[k] += __shfl_xor_sync(0xffffffffu, ax1[k], o);
            }
            d0 += __shfl_xor_sync(0xffffffffu, d0, o);
            d1 += __shfl_xor_sync(0xffffffffu, d1, o);
        }
        float inv0 = 1.0f / (d0 + 1e-16f);
        float inv1 = 1.0f / (d1 + 1e-16f);

        int head = lane >> 4;
        float axs[8];
#pragma unroll
        for (int k = 0; k < 8; k++) axs[k] = head ? (ax1[k] * inv1) : (ax0[k] * inv0);

        float o4[4];
#pragma unroll
        for (int v = 0; v < 4; v++) {
            int dim = lane * 4 + v;
            float s = bias[dim];
#pragma unroll
            for (int k = 0; k < 8; k++) s += axs[k] * Wsh[k * 128 + dim];
            o4[v] = s > 0.f ? s : expm1f(s);
        }
        st_h4(&g_xb[(size_t)node * 128 + lane * 4], o4);
    }
}

// =================== tensor-core big GEMM (128 -> HC) via wmma bf16 ===================
template <int HC>
__global__ void __launch_bounds__(256) k_gemm_wmma(const float* __restrict__ W,
                                                   const float* __restrict__ asrc,
                                                   const float* __restrict__ adst) {
    constexpr int MTILE = (HC == 128) ? 64 : 128;
    constexpr int H     = (HC == 128) ? 2 : 1;
    constexpr int XLD   = 136;
    constexpr int WLD   = (HC == 128) ? 136 : 72;
    constexpr int SLD   = 68;

    extern __shared__ char smem[];
    __nv_bfloat16* xs  = reinterpret_cast<__nv_bfloat16*>(smem);
    __nv_bfloat16* Wsh = xs + MTILE * XLD;
    float*         stg = reinterpret_cast<float*>(Wsh + 128 * WLD);

    int tid = threadIdx.x, lane = tid & 31, w = tid >> 5;
    int r = (HC == 128) ? (w >> 1) : w;
    int c = (HC == 128) ? (w & 1) : 0;
    int base = blockIdx.x * MTILE;

    for (int i = tid; i < 128 * HC / 2; i += 256) {
        int k = (i * 2) / HC, n = (i * 2) % HC;
        float2 wv = *reinterpret_cast<const float2*>(&W[k * HC + n]);
        *reinterpret_cast<__nv_bfloat162*>(&Wsh[k * WLD + n]) = __floats2bfloat162_rn(wv.x, wv.y);
    }
    for (int i = tid; i < MTILE * 16; i += 256) {
        int m = i / 16, q = i % 16;
        int node = base + m;
        uint4 v = (node < NN)
            ? *reinterpret_cast<const uint4*>(&g_xb[(size_t)node * 128 + q * 8])
            : make_uint4(0u, 0u, 0u, 0u);
        *reinterpret_cast<uint4*>(&xs[m * XLD + q * 8]) = v;
    }
    __syncthreads();

    wmma::fragment<wmma::accumulator, 16, 16, 16, float> acc[4];
#pragma unroll
    for (int j = 0; j < 4; j++) wmma::fill_fragment(acc[j], 0.f);

#pragma unroll
    for (int k0 = 0; k0 < 8; k0++) {
        wmma::fragment<wmma::matrix_a, 16, 16, 16, __nv_bfloat16, wmma::row_major> af;
        wmma::load_matrix_sync(af, &xs[(r * 16) * XLD + k0 * 16], XLD);
#pragma unroll
        for (int j = 0; j < 4; j++) {
            wmma::fragment<wmma::matrix_b, 16, 16, 16, __nv_bfloat16, wmma::row_major> bf;
            wmma::load_matrix_sync(bf, &Wsh[(k0 * 16) * WLD + c * 64 + j * 16], WLD);
            wmma::mma_sync(acc[j], af, bf, acc[j]);
        }
    }

    float* st = stg + w * 16 * SLD;
#pragma unroll
    for (int j = 0; j < 4; j++)
        wmma::store_matrix_sync(&st[j * 16], acc[j], SLD, wmma::mem_row_major);
    __syncwarp();

    float as_lo = asrc[c * 64 + lane], as_hi = asrc[c * 64 + lane + 32];
    float ad_lo = adst[c * 64 + lane], ad_hi = adst[c * 64 + lane + 32];

#pragma unroll
    for (int i = 0; i < 16; i++) {
        int node = base + r * 16 + i;
        if (node >= NN) break;
        float2 hv = *reinterpret_cast<const float2*>(&st[i * SLD + lane * 2]);
        st_h2(&g_h[(size_t)node * HC + c * 64 + lane * 2], hv.x, hv.y);
        float e0 = st[i * SLD + lane], e1 = st[i * SLD + lane + 32];
        float vs = e0 * as_lo + e1 * as_hi;
        float vd = e0 * ad_lo + e1 * ad_hi;
#pragma unroll
        for (int o = 16; o > 0; o >>= 1) {
            vs += __shfl_down_sync(0xffffffffu, vs, o);
            vd += __shfl_down_sync(0xffffffffu, vd, o);
        }
        if (lane == 0) {
            g_as[node * H + c] = vs;
            g_ad[node * H + c] = vd;
        }
    }
}

// =================== fused softmax-aggregate (grid-stride warps) ===================
template <int HC, int H, bool ACT, bool POOL>
__global__ void __launch_bounds__(256) k_agg(const float* __restrict__ bias,
                                             const int* __restrict__ batch) {
    constexpr int VEC = HC / 32;
    constexpr int ROWB = HC * 2;
    __shared__ __align__(16) unsigned long long s_rec[8][32 * H];
    int lane = threadIdx.x & 31, wp = threadIdx.x >> 5;
    int head = (H == 2) ? (lane >> 4) : 0;
    const int stride = gridDim.x * 8;
    const char* hb_lane = reinterpret_cast<const char*>(g_h) + lane * ((VEC == 4) ? 8 : 4);

    for (int node = blockIdx.x * 8 + wp; node < NN; node += stride) {
        float ad0 = g_ad[node * H];
        float ad1 = (H == 2) ? g_ad[node * H + 1] : 0.f;
        int beg = g_off[node], end = g_off[node + 1];

        float acc[VEC];
#pragma unroll
        for (int v = 0; v < VEC; v++) acc[v] = 0.f;
        float d0 = 0.f, d1 = 0.f;

        for (int chunk = beg; chunk < end; chunk += 32) {
            int i = chunk + lane;
            if (i < end) {
                int s = g_csr[i];
                unsigned soff = (unsigned)s * ROWB;
                if (H == 2) {
                    float2 a = *reinterpret_cast<const float2*>(&g_as[s * 2]);
                    float w0 = __expf(lrelu(a.x + ad0));
                    float w1 = __expf(lrelu(a.y + ad1));
                    d0 += w0; d1 += w1;
                    *reinterpret_cast<ulonglong2*>(&s_rec[wp][lane * 2]) =
                        make_ulonglong2(pack2u(soff, w0), pack2u(soff, w1));
                } else {
                    float w0 = __expf(lrelu(g_as[s] + ad0));
                    d0 += w0;
                    s_rec[wp][lane] = pack2u(soff, w0);
                }
            }
            __syncwarp();
            int cnt = min(32, end - chunk);
            int j = 0;
            for (; j + 8 <= cnt; j += 8) {
                unsigned soff[8];
                float    ww[8];
#pragma unroll
                for (int u = 0; u < 8; u++) {
                    unsigned long long rec = (H == 2) ? s_rec[wp][(j + u) * 2 + head]
                                                      : s_rec[wp][j + u];
                    unpack2u(rec, soff[u], ww[u]);
                }
                if (VEC == 4) {
                    uint2 hv[8];
#pragma unroll
                    for (int u = 0; u < 8; u++)
                        hv[u] = *reinterpret_cast<const uint2*>(hb_lane + soff[u]);
#pragma unroll
                    for (int u = 0; u < 8; u++) acc_h4(acc, hv[u].x, hv[u].y, ww[u]);
                } else {
                    unsigned hv[8];
#pragma unroll
                    for (int u = 0; u < 8; u++)
                        hv[u] = *reinterpret_cast<const unsigned*>(hb_lane + soff[u]);
#pragma unroll
                    for (int u = 0; u < 8; u++) acc_h2(acc, hv[u], ww[u]);
                }
            }
            for (; j + 4 <= cnt; j += 4) {
                unsigned soff[4];
                float    ww[4];
#pragma unroll
                for (int u = 0; u < 4; u++) {
                    unsigned long long rec = (H == 2) ? s_rec[wp][(j + u) * 2 + head]
                                                      : s_rec[wp][j + u];
                    unpack2u(rec, soff[u], ww[u]);
                }
                if (VEC == 4) {
                    uint2 hv[4];
#pragma unroll
                    for (int u = 0; u < 4; u++)
                        hv[u] = *reinterpret_cast<const uint2*>(hb_lane + soff[u]);
#pragma unroll
                    for (int u = 0; u < 4; u++) acc_h4(acc, hv[u].x, hv[u].y, ww[u]);
                } else {
                    unsigned hv[4];
#pragma unroll
                    for (int u = 0; u < 4; u++)
                        hv[u] = *reinterpret_cast<const unsigned*>(hb_lane + soff[u]);
#pragma unroll
                    for (int u = 0; u < 4; u++) acc_h2(acc, hv[u], ww[u]);
                }
            }
            for (; j < cnt; j++) {
                unsigned long long rec = (H == 2) ? s_rec[wp][j * 2 + head] : s_rec[wp][j];
                unsigned soff; float w;
                unpack2u(rec, soff, w);
                if (VEC == 4) {
                    uint2 hv = *reinterpret_cast<const uint2*>(hb_lane + soff);
                    acc_h4(acc, hv.x, hv.y, w);
                } else {
                    unsigned hv = *reinterpret_cast<const unsigned*>(hb_lane + soff);
                    acc_h2(acc, hv, w);
                }
            }
            __syncwarp();
        }

        float ws = __expf(lrelu(g_as[node * H + head] + ((H == 2 && head) ? ad1 : ad0)));
        {
            unsigned soff = (unsigned)node * ROWB;
            if (VEC == 4) {
                uint2 hv = *reinterpret_cast<const uint2*>(hb_lane + soff);
                acc_h4(acc, hv.x, hv.y, ws);
            } else {
                unsigned hv = *reinterpret_cast<const unsigned*>(hb_lane + soff);
                acc_h2(acc, hv, ws);
            }
        }

#pragma unroll
        for (int o = 16; o > 0; o >>= 1) {
            d0 += __shfl_xor_sync(0xffffffffu, d0, o);
            if (H == 2) d1 += __shfl_xor_sync(0xffffffffu, d1, o);
        }
        float dh = (H == 2 && head) ? d1 : d0;
        float inv = 1.0f / (dh + ws + 1e-16f);

        float outv[VEC];
#pragma unroll
        for (int v = 0; v < VEC; v++) {
            float t = acc[v] * inv + bias[lane * VEC + v];
            if (ACT) t = t > 0.f ? t : expm1f(t);
            outv[v] = t;
        }

        if (POOL) {
            int b = batch[node];
            float o2 = __shfl_down_sync(0xffffffffu, outv[0], 1);
            float o3 = __shfl_down_sync(0xffffffffu, outv[VEC - 1], 1);
            if ((lane & 1) == 0)
                red4(&g_pool[b * 64 + lane * 2], outv[0], outv[VEC - 1], o2, o3);
        } else {
            if (VEC == 4) st_h4(&g_xb[(size_t)node * HC + lane * 4], outv);
            else          st_h2(&g_xb[(size_t)node * HC + lane * 2], outv[0], outv[1]);
        }
    }
}

// =================== MLP head ===================
__global__ void k_mlp(const int* __restrict__ batch,
                      const float* __restrict__ obs,
                      const float* __restrict__ Ws1, const float* __restrict__ bs1,
                      const float* __restrict__ lng, const float* __restrict__ lnb,
                      const float* __restrict__ Ws2, const float* __restrict__ bs2,
                      const float* __restrict__ Wa,  const float* __restrict__ ba,
                      const float* __restrict__ Wc,  const float* __restrict__ bc,
                      float* __restrict__ out) {
    __shared__ float comb[64 + OBSD];
    __shared__ float hb[MHD];
    __shared__ float h2[MHD];
    __shared__ float rb[8];
    __shared__ float stats[2];
    __shared__ float s_cnt;

    int b = blockIdx.x;
    int tid = threadIdx.x;

    if (tid == 0) {
        int lo = 0, hi = NN;
        while (lo < hi) { int m = (lo + hi) >> 1; if (batch[m] < b) lo = m + 1; else hi = m; }
        int st = lo; lo = 0; hi = NN;
        while (lo < hi) { int m = (lo + hi) >> 1; if (batch[m] < b + 1) lo = m + 1; else hi = m; }
        s_cnt = (float)(lo - st);
    }
    __syncthreads();

    if (tid < 64)             comb[tid] = g_pool[b * 64 + tid] / fmaxf(s_cnt, 1.0f);
    else if (tid < 64 + OBSD) comb[tid] = obs[b * OBSD + (tid - 64)];
    __syncthreads();

    float s = bs1[tid];
    for (int k = 0; k < 64 + OBSD; k++) s += comb[k] * Ws1[k * MHD + tid];

    float v = s;
#pragma unroll
    for (int o = 16; o > 0; o >>= 1) v += __shfl_down_sync(0xffffffffu, v, o);
    if ((tid & 31) == 0) rb[tid >> 5] = v;
    __syncthreads();
    if (tid == 0) { float t = 0.f; for (int w = 0; w < 8; w++) t += rb[w]; stats[0] = t / MHD; }
    __syncthreads();
    float mu = stats[0];
    float dv = s - mu;
    v = dv * dv;
#pragma unroll
    for (int o = 16; o > 0; o >>= 1) v += __shfl_down_sync(0xffffffffu, v, o);
    if ((tid & 31) == 0) rb[tid >> 5] = v;
    __syncthreads();
    if (tid == 0) { float t = 0.f; for (int w = 0; w < 8; w++) t += rb[w]; stats[1] = t / MHD; }
    __syncthreads();

    float hn = dv * rsqrtf(stats[1] + 1e-5f) * lng[tid] + lnb[tid];
    hb[tid] = fmaxf(hn, 0.f);
    __syncthreads();

    float s2 = bs2[tid];
    for (int k = 0; k < MHD; k++) s2 += hb[k] * Ws2[k * MHD + tid];
    h2[tid] = fmaxf(s2, 0.f);
    __syncthreads();

    if (tid < NAD) {
        float t = ba[tid];
        for (int k = 0; k < MHD; k++) t += h2[k] * Wa[k * NAD + tid];
        out[b * NAD + tid] = t;
    }
    if (tid == NAD) {
        float t = bc[0];
        for (int k = 0; k < MHD; k++) t += h2[k] * Wc[k];
        out[BB * NAD + b] = t;
    }
}

// =================== launch ===================
static inline int gs(long long n) { return (int)((n + 255) / 256); }

extern "C" void kernel_launch(void* const* d_in, const int* in_sizes, int n_in,
                              void* d_out, int out_size) {
    const float* obs   = (const float*)d_in[0];
    const float* nf    = (const float*)d_in[1];
    const int*   ei    = (const int*)  d_in[2];
    const int*   batch = (const int*)  d_in[3];
    const float* W0 = (const float*)d_in[4];
    const float* as0 = (const float*)d_in[5];
    const float* ad0 = (const float*)d_in[6];
    const float* b0  = (const float*)d_in[7];
    const float* W1 = (const float*)d_in[8];
    const float* as1 = (const float*)d_in[9];
    const float* ad1 = (const float*)d_in[10];
    const float* b1  = (const float*)d_in[11];
    const float* W2 = (const float*)d_in[12];
    const float* as2 = (const float*)d_in[13];
    const float* ad2 = (const float*)d_in[14];
    const float* b2  = (const float*)d_in[15];
    const float* Ws1 = (const float*)d_in[16];
    const float* bs1 = (const float*)d_in[17];
    const float* lng = (const float*)d_in[18];
    const float* lnb = (const float*)d_in[19];
    const float* Ws2 = (const float*)d_in[20];
    const float* bs2 = (const float*)d_in[21];
    const float* Wa  = (const float*)d_in[22];
    const float* ba  = (const float*)d_in[23];
    const float* Wc  = (const float*)d_in[24];
    const float* bc  = (const float*)d_in[25];
    float* out = (float*)d_out;

    void *p_deg, *p_pool;
    cudaGetSymbolAddress(&p_deg,  g_deg);
    cudaGetSymbolAddress(&p_pool, g_pool);

    const int SM128 = (64 * 136 + 128 * 136) * 2 + 8 * 16 * 68 * 4;   // 87040
    const int SM64  = (128 * 136 + 128 * 72) * 2 + 8 * 16 * 68 * 4;   // 88064
    cudaFuncSetAttribute(k_gemm_wmma<128>, cudaFuncAttributeMaxDynamicSharedMemorySize, SM128);
    cudaFuncSetAttribute(k_gemm_wmma<64>,  cudaFuncAttributeMaxDynamicSharedMemorySize, SM64);

    cudaStream_t s2;
    cudaEvent_t evF, evJ;
    cudaStreamCreateWithFlags(&s2, cudaStreamNonBlocking);
    cudaEventCreateWithFlags(&evF, cudaEventDisableTiming);
    cudaEventCreateWithFlags(&evJ, cudaEventDisableTiming);

    cudaMemsetAsync(p_deg,  0, (NN + 1) * sizeof(int));
    cudaMemsetAsync(p_pool, 0, BB * 64 * sizeof(float));

    cudaEventRecord(evF, 0);
    cudaStreamWaitEvent(s2, evF, 0);
    k_prep0<<<196, 256, 0, s2>>>(nf, W0, as0, ad0);      // side stream: alpha0 + bf16 x8

    k_hist<<<gs(EE / 8), 256>>>(ei);                      // main stream: CSR chain
    k_scan<<<1, 1024>>>();
    k_fill<<<gs(EE / 8), 256>>>(ei);

    cudaEventRecord(evJ, s2);
    cudaStreamWaitEvent(0, evJ, 0);                       // join before agg0x

    const int AGGB = 1563;

    k_agg0x<<<AGGB, 256>>>(W0, b0);                       // layer-0 agg on 8-dim x + W0 transform
    k_gemm_wmma<128><<<782, 256, SM128>>>(W1, as1, ad1);
    k_agg<128, 2, true, false><<<AGGB, 256>>>(b1, nullptr);
    k_gemm_wmma<64><<<391, 256, SM64>>>(W2, as2, ad2);
    k_agg<64, 1, false, true><<<AGGB, 256>>>(b2, batch);
    k_mlp<<<BB, MHD>>>(batch, obs, Ws1, bs1, lng, lnb, Ws2, bs2, Wa, ba, Wc, bc, out);
}